// round 1
// baseline (speedup 1.0000x reference)
#include <cuda_runtime.h>
#include <math.h>

#define HEADS   8
#define DHEAD   64
#define C_DIM   512
#define BATCH   2
#define HW      2304          // 48*48
#define BN      (BATCH*HEADS) // 16

// Scratch (no cudaMalloc allowed): Q,K,V,O each [BN][HW][DHEAD] fp32 (~9.4MB ea)
__device__ float g_Q[BN * HW * DHEAD];
__device__ float g_K[BN * HW * DHEAD];
__device__ float g_V[BN * HW * DHEAD];
__device__ float g_O[BN * HW * DHEAD];

// ---------------------------------------------------------------------------
// Kernel 1: QKV projection.
// Q[bn][s][d] = (sum_c x[b][c][s] * W[n][d][c] + bias[n][d]) * (q? 0.125 : 1)
// grid: (36 s-tiles, 16 bn, 3 which), block 256 (16x16), 64x64 tile, BK=32.
// ---------------------------------------------------------------------------
__global__ __launch_bounds__(256) void qkv_kernel(
    const float* __restrict__ X,
    const float* __restrict__ Wq, const float* __restrict__ bq,
    const float* __restrict__ Wk, const float* __restrict__ bk,
    const float* __restrict__ Wv, const float* __restrict__ bv)
{
    __shared__ float Xs[32 * 64];    // Xs[kk][sl]
    __shared__ float Ws[64 * 33];    // Ws[d][kk], pad 33

    const int which = blockIdx.z;
    const float* W    = (which == 0) ? Wq : (which == 1) ? Wk : Wv;
    const float* bias = (which == 0) ? bq : (which == 1) ? bk : bv;
    float* Out        = (which == 0) ? g_Q : (which == 1) ? g_K : g_V;

    const int bn = blockIdx.y;
    const int b  = bn >> 3;
    const int n  = bn & 7;
    const int s0 = blockIdx.x * 64;

    const int tid = threadIdx.x;
    const int ty  = tid >> 4;   // s micro dim
    const int tx  = tid & 15;   // d micro dim

    float acc[4][4] = {};

    for (int k0 = 0; k0 < C_DIM; k0 += 32) {
        #pragma unroll
        for (int t = 0; t < 8; t++) {
            int idx = tid + t * 256;
            int kk = idx >> 6, sl = idx & 63;
            Xs[idx] = X[((size_t)b * C_DIM + k0 + kk) * HW + s0 + sl];
        }
        #pragma unroll
        for (int t = 0; t < 8; t++) {
            int idx = tid + t * 256;
            int d = idx >> 5, kk = idx & 31;
            Ws[d * 33 + kk] = W[((size_t)n * DHEAD + d) * C_DIM + k0 + kk];
        }
        __syncthreads();

        #pragma unroll
        for (int kk = 0; kk < 32; kk++) {
            float xf[4], wf[4];
            #pragma unroll
            for (int i = 0; i < 4; i++) xf[i] = Xs[kk * 64 + ty + i * 16];
            #pragma unroll
            for (int j = 0; j < 4; j++) wf[j] = Ws[(tx + j * 16) * 33 + kk];
            #pragma unroll
            for (int i = 0; i < 4; i++)
                #pragma unroll
                for (int j = 0; j < 4; j++)
                    acc[i][j] += xf[i] * wf[j];
        }
        __syncthreads();
    }

    const float scale = (which == 0) ? 0.125f : 1.0f;  // 1/sqrt(64) folded into Q
    #pragma unroll
    for (int i = 0; i < 4; i++) {
        int s = s0 + ty + i * 16;
        #pragma unroll
        for (int j = 0; j < 4; j++) {
            int d = tx + j * 16;
            Out[((size_t)bn * HW + s) * DHEAD + d] =
                (acc[i][j] + bias[n * DHEAD + d]) * scale;
        }
    }
}

// ---------------------------------------------------------------------------
// Kernel 2: flash attention. One block per (64-row q-tile, bn). 36 k-tiles.
// S = Qs @ Ks^T (Q pre-scaled), online softmax, O += P @ Vs, final /= l.
// ---------------------------------------------------------------------------
#define ATTN_SMEM_FLOATS (4 * 64 * 65 + 128)
#define ATTN_SMEM_BYTES  (ATTN_SMEM_FLOATS * 4)

__global__ __launch_bounds__(256) void attn_kernel()
{
    extern __shared__ float sm[];
    float* Qs   = sm;                 // [64][65]
    float* Ks   = Qs + 64 * 65;       // [64][65]
    float* Vs   = Ks + 64 * 65;       // [64][65]
    float* Ss   = Vs + 64 * 65;       // [64][65]
    float* rowf = Ss + 64 * 65;       // [64] corr factor
    float* rowl = rowf + 64;          // [64] final l

    const int bn = blockIdx.y;
    const int q0 = blockIdx.x * 64;
    const int tid = threadIdx.x;
    const int ty = tid >> 4;          // q micro dim
    const int tx = tid & 15;          // kv / d micro dim

    #pragma unroll
    for (int t = 0; t < 16; t++) {
        int idx = tid + t * 256;
        int r = idx >> 6, d = idx & 63;
        Qs[r * 65 + d] = g_Q[((size_t)bn * HW + q0 + r) * DHEAD + d];
    }

    float o_acc[4][4] = {};
    float m_run = -1e30f, l_run = 0.0f;   // valid only on tid<64

    for (int kt = 0; kt < HW / 64; kt++) {
        __syncthreads();  // prior iter done reading Ss/Vs (and Qs ready 1st iter)
        #pragma unroll
        for (int t = 0; t < 16; t++) {
            int idx = tid + t * 256;
            int r = idx >> 6, d = idx & 63;
            size_t base = ((size_t)bn * HW + (size_t)kt * 64 + r) * DHEAD + d;
            Ks[r * 65 + d] = g_K[base];
            Vs[r * 65 + d] = g_V[base];
        }
        __syncthreads();

        // S = Q @ K^T
        float s_acc[4][4] = {};
        #pragma unroll
        for (int kk = 0; kk < 64; kk++) {
            float qf[4], kf[4];
            #pragma unroll
            for (int i = 0; i < 4; i++) qf[i] = Qs[(ty + i * 16) * 65 + kk];
            #pragma unroll
            for (int j = 0; j < 4; j++) kf[j] = Ks[(tx + j * 16) * 65 + kk];
            #pragma unroll
            for (int i = 0; i < 4; i++)
                #pragma unroll
                for (int j = 0; j < 4; j++)
                    s_acc[i][j] += qf[i] * kf[j];
        }
        #pragma unroll
        for (int i = 0; i < 4; i++)
            #pragma unroll
            for (int j = 0; j < 4; j++)
                Ss[(ty + i * 16) * 65 + (tx + j * 16)] = s_acc[i][j];
        __syncthreads();

        // Online softmax: one thread per row (stride-65 rows -> conflict-free)
        if (tid < 64) {
            float mx = m_run;
            #pragma unroll 8
            for (int j2 = 0; j2 < 64; j2++) mx = fmaxf(mx, Ss[tid * 65 + j2]);
            float corr = __expf(m_run - mx);
            float sum = 0.0f;
            #pragma unroll 8
            for (int j2 = 0; j2 < 64; j2++) {
                float p = __expf(Ss[tid * 65 + j2] - mx);
                Ss[tid * 65 + j2] = p;
                sum += p;
            }
            m_run = mx;
            l_run = l_run * corr + sum;
            rowf[tid] = corr;
        }
        __syncthreads();

        // O = O*corr + P @ V
        #pragma unroll
        for (int i = 0; i < 4; i++) {
            float c = rowf[ty + i * 16];
            #pragma unroll
            for (int j = 0; j < 4; j++) o_acc[i][j] *= c;
        }
        #pragma unroll
        for (int kk = 0; kk < 64; kk++) {
            float pf[4], vf[4];
            #pragma unroll
            for (int i = 0; i < 4; i++) pf[i] = Ss[(ty + i * 16) * 65 + kk];
            #pragma unroll
            for (int j = 0; j < 4; j++) vf[j] = Vs[kk * 65 + tx + j * 16];
            #pragma unroll
            for (int i = 0; i < 4; i++)
                #pragma unroll
                for (int j = 0; j < 4; j++)
                    o_acc[i][j] += pf[i] * vf[j];
        }
    }

    __syncthreads();
    if (tid < 64) rowl[tid] = l_run;
    __syncthreads();

    #pragma unroll
    for (int i = 0; i < 4; i++) {
        float inv = 1.0f / rowl[ty + i * 16];
        int q = q0 + ty + i * 16;
        #pragma unroll
        for (int j = 0; j < 4; j++) {
            int d = tx + j * 16;
            g_O[((size_t)bn * HW + q) * DHEAD + d] = o_acc[i][j] * inv;
        }
    }
}

// ---------------------------------------------------------------------------
// Kernel 3: output projection + head concat + NCHW transpose.
// out[b][c][s] = bo[c] + sum_hd O[b][hd/64][s][hd%64] * Wo[c][hd]
// grid: (36 s-tiles, 8 c-tiles, 2 b), block 256, 64x64 tile, BK=32.
// ---------------------------------------------------------------------------
__global__ __launch_bounds__(256) void proj_kernel(
    const float* __restrict__ Wo, const float* __restrict__ bo,
    float* __restrict__ out)
{
    __shared__ float As[64 * 33];   // As[sl][kk]
    __shared__ float Ws[64 * 33];   // Ws[cl][kk]

    const int b  = blockIdx.z;
    const int c0 = blockIdx.y * 64;
    const int s0 = blockIdx.x * 64;
    const int tid = threadIdx.x;
    const int ty = tid >> 4;  // c micro dim
    const int tx = tid & 15;  // s micro dim

    float acc[4][4] = {};

    for (int k0 = 0; k0 < C_DIM; k0 += 32) {
        int n  = k0 >> 6;      // BK=32 never crosses a head boundary
        int d0 = k0 & 63;
        #pragma unroll
        for (int t = 0; t < 8; t++) {
            int idx = tid + t * 256;
            int sl = idx >> 5, kk = idx & 31;
            As[sl * 33 + kk] =
                g_O[((size_t)(b * HEADS + n) * HW + s0 + sl) * DHEAD + d0 + kk];
        }
        #pragma unroll
        for (int t = 0; t < 8; t++) {
            int idx = tid + t * 256;
            int cl = idx >> 5, kk = idx & 31;
            Ws[cl * 33 + kk] = Wo[(size_t)(c0 + cl) * C_DIM + k0 + kk];
        }
        __syncthreads();

        #pragma unroll
        for (int kk = 0; kk < 32; kk++) {
            float af[4], wf[4];
            #pragma unroll
            for (int j = 0; j < 4; j++) af[j] = As[(tx + j * 16) * 33 + kk];
            #pragma unroll
            for (int i = 0; i < 4; i++) wf[i] = Ws[(ty + i * 16) * 33 + kk];
            #pragma unroll
            for (int i = 0; i < 4; i++)
                #pragma unroll
                for (int j = 0; j < 4; j++)
                    acc[i][j] += wf[i] * af[j];
        }
        __syncthreads();
    }

    #pragma unroll
    for (int i = 0; i < 4; i++) {
        int c = c0 + ty + i * 16;
        float bias = bo[c];
        #pragma unroll
        for (int j = 0; j < 4; j++) {
            int s = s0 + tx + j * 16;
            out[((size_t)b * C_DIM + c) * HW + s] = acc[i][j] + bias;
        }
    }
}

// ---------------------------------------------------------------------------
extern "C" void kernel_launch(void* const* d_in, const int* in_sizes, int n_in,
                              void* d_out, int out_size)
{
    const float* X  = (const float*)d_in[0];
    const float* Wq = (const float*)d_in[1];
    const float* bq = (const float*)d_in[2];
    const float* Wk = (const float*)d_in[3];
    const float* bk = (const float*)d_in[4];
    const float* Wv = (const float*)d_in[5];
    const float* bv = (const float*)d_in[6];
    const float* Wo = (const float*)d_in[7];
    const float* bo = (const float*)d_in[8];
    float* out = (float*)d_out;

    cudaFuncSetAttribute(attn_kernel,
                         cudaFuncAttributeMaxDynamicSharedMemorySize,
                         ATTN_SMEM_BYTES);

    qkv_kernel<<<dim3(HW / 64, BN, 3), 256>>>(X, Wq, bq, Wk, bk, Wv, bv);
    attn_kernel<<<dim3(HW / 64, BN), 256, ATTN_SMEM_BYTES>>>();
    proj_kernel<<<dim3(HW / 64, C_DIM / 64, BATCH), 256>>>(Wo, bo, out);
}

// round 2
// speedup vs baseline: 2.4474x; 2.4474x over previous
#include <cuda_runtime.h>
#include <math.h>
#include <stdint.h>

#define HEADS   8
#define DHEAD   64
#define C_DIM   512
#define BATCH   2
#define HW      2304          // 48*48
#define BN      (BATCH*HEADS) // 16

// Scratch (no cudaMalloc allowed): Q,K,V,O each [BN][HW][DHEAD] fp32 (~9.4MB ea)
// Values stored are tf32-rounded so consumers can reinterpret bits directly.
__device__ float g_Q[BN * HW * DHEAD];
__device__ float g_K[BN * HW * DHEAD];
__device__ float g_V[BN * HW * DHEAD];
__device__ float g_O[BN * HW * DHEAD];

// ---------------------------------------------------------------------------
// tf32 helpers
// ---------------------------------------------------------------------------
__device__ __forceinline__ uint32_t f2tf(float x) {
    uint32_t u;
    asm("cvt.rna.tf32.f32 %0, %1;" : "=r"(u) : "f"(x));
    return u;
}

__device__ __forceinline__ void mma8(float* c,
                                     uint32_t a0, uint32_t a1, uint32_t a2, uint32_t a3,
                                     uint32_t b0, uint32_t b1) {
    asm volatile(
        "mma.sync.aligned.m16n8k8.row.col.f32.tf32.tf32.f32 "
        "{%0,%1,%2,%3}, {%4,%5,%6,%7}, {%8,%9}, {%0,%1,%2,%3};"
        : "+f"(c[0]), "+f"(c[1]), "+f"(c[2]), "+f"(c[3])
        : "r"(a0), "r"(a1), "r"(a2), "r"(a3), "r"(b0), "r"(b1));
}

// ---------------------------------------------------------------------------
// Kernel 1: QKV projection (tf32 mma).
// Q[bn][s][d] = (sum_c X[b][c][s] * W[n][d][c] + bias[n][d]) * (q? 0.125 : 1)
// Block 256 (8 warps, 4x2 m-n layout), tile 64(s) x 64(d), BK=32.
// ---------------------------------------------------------------------------
__global__ __launch_bounds__(256) void qkv_kernel(
    const float* __restrict__ X,
    const float* __restrict__ Wq, const float* __restrict__ bq,
    const float* __restrict__ Wk, const float* __restrict__ bk,
    const float* __restrict__ Wv, const float* __restrict__ bv)
{
    __shared__ uint32_t Xs[32 * 68];   // Xs[kk][sl], stride 68 (conflict-free frags)
    __shared__ uint32_t Ws[64 * 36];   // Ws[d][kk],  stride 36

    const int which = blockIdx.z;
    const float* W    = (which == 0) ? Wq : (which == 1) ? Wk : Wv;
    const float* bias = (which == 0) ? bq : (which == 1) ? bk : bv;
    float* Out        = (which == 0) ? g_Q : (which == 1) ? g_K : g_V;

    const int bn = blockIdx.y;
    const int b  = bn >> 3;
    const int n  = bn & 7;
    const int s0 = blockIdx.x * 64;

    const int tid    = threadIdx.x;
    const int wid    = tid >> 5;
    const int lane   = tid & 31;
    const int lg     = lane >> 2;     // group id 0..7
    const int lt     = lane & 3;      // thread-in-group 0..3
    const int warp_m = wid >> 1;      // 0..3 (s)
    const int warp_n = wid & 1;       // 0..1 (d)

    float acc[4][4] = {};             // [nt][c-frag]

    for (int k0 = 0; k0 < C_DIM; k0 += 32) {
        #pragma unroll
        for (int t = 0; t < 8; t++) {
            int idx = tid + t * 256;
            int kk = idx >> 6, sl = idx & 63;
            Xs[kk * 68 + sl] = f2tf(X[((size_t)b * C_DIM + k0 + kk) * HW + s0 + sl]);
        }
        #pragma unroll
        for (int t = 0; t < 8; t++) {
            int idx = tid + t * 256;
            int d = idx >> 5, kk = idx & 31;
            Ws[d * 36 + kk] = f2tf(W[((size_t)n * DHEAD + d) * C_DIM + k0 + kk]);
        }
        __syncthreads();

        #pragma unroll
        for (int ks = 0; ks < 4; ks++) {
            const int kb = ks * 8;
            const int srow = warp_m * 16 + lg;
            uint32_t a0 = Xs[(kb + lt) * 68 + srow];
            uint32_t a1 = Xs[(kb + lt) * 68 + srow + 8];
            uint32_t a2 = Xs[(kb + lt + 4) * 68 + srow];
            uint32_t a3 = Xs[(kb + lt + 4) * 68 + srow + 8];
            #pragma unroll
            for (int nt = 0; nt < 4; nt++) {
                int dcol = warp_n * 32 + nt * 8 + lg;
                uint32_t b0 = Ws[dcol * 36 + kb + lt];
                uint32_t b1 = Ws[dcol * 36 + kb + lt + 4];
                mma8(acc[nt], a0, a1, a2, a3, b0, b1);
            }
        }
        __syncthreads();
    }

    const float scale = (which == 0) ? 0.125f : 1.0f;   // 1/sqrt(64) folded into Q
    const int row0 = s0 + warp_m * 16 + lg;
    #pragma unroll
    for (int nt = 0; nt < 4; nt++) {
        int col = warp_n * 32 + nt * 8 + 2 * lt;
        float b0f = bias[n * DHEAD + col];
        float b1f = bias[n * DHEAD + col + 1];
        float v00 = (acc[nt][0] + b0f) * scale;
        float v01 = (acc[nt][1] + b1f) * scale;
        float v10 = (acc[nt][2] + b0f) * scale;
        float v11 = (acc[nt][3] + b1f) * scale;
        // store tf32-rounded so attn can reinterpret bits without cvt
        float2 lo = make_float2(__uint_as_float(f2tf(v00)), __uint_as_float(f2tf(v01)));
        float2 hi = make_float2(__uint_as_float(f2tf(v10)), __uint_as_float(f2tf(v11)));
        *(float2*)&Out[((size_t)bn * HW + row0)     * DHEAD + col] = lo;
        *(float2*)&Out[((size_t)bn * HW + row0 + 8) * DHEAD + col] = hi;
    }
}

// ---------------------------------------------------------------------------
// Kernel 2: flash attention with tf32 mma.
// Block per (64-row q-tile, bn); 36 kv tiles of 64; online softmax in fp32.
// ---------------------------------------------------------------------------
#define ATTN_SMEM_WORDS (4 * 64 * 68 + 192)
#define ATTN_SMEM_BYTES (ATTN_SMEM_WORDS * 4)

__global__ __launch_bounds__(256) void attn_kernel()
{
    extern __shared__ uint32_t sm[];
    uint32_t* Qs = sm;                       // [64][68] tf32 bits
    uint32_t* Ks = Qs + 64 * 68;             // [64][68]
    uint32_t* Vs = Ks + 64 * 68;             // [64][68]
    float*    Ss = (float*)(Vs + 64 * 68);   // [64][68] scores, then P (tf32 bits)
    float*    rowm = Ss + 64 * 68;           // [64]
    float*    rowl = rowm + 64;              // [64]
    float*    rowf = rowl + 64;              // [64]

    const int bn = blockIdx.y;
    const int q0 = blockIdx.x * 64;
    const int tid    = threadIdx.x;
    const int wid    = tid >> 5;
    const int lane   = tid & 31;
    const int lg     = lane >> 2;
    const int lt     = lane & 3;
    const int warp_m = wid >> 1;
    const int warp_n = wid & 1;

    #pragma unroll
    for (int t = 0; t < 16; t++) {
        int idx = tid + t * 256;
        int r = idx >> 6, d = idx & 63;
        Qs[r * 68 + d] = __float_as_uint(g_Q[((size_t)bn * HW + q0 + r) * DHEAD + d]);
    }
    if (tid < 64) { rowm[tid] = -1e30f; rowl[tid] = 0.0f; }

    float o_acc[4][4] = {};

    for (int kt = 0; kt < HW / 64; kt++) {
        __syncthreads();   // also covers Qs/rowm readiness on first iter
        #pragma unroll
        for (int t = 0; t < 16; t++) {
            int idx = tid + t * 256;
            int r = idx >> 6, d = idx & 63;
            size_t base = ((size_t)bn * HW + (size_t)kt * 64 + r) * DHEAD + d;
            Ks[r * 68 + d] = __float_as_uint(g_K[base]);
            Vs[r * 68 + d] = __float_as_uint(g_V[base]);
        }
        __syncthreads();

        // ---- S = Q @ K^T  (m16n32 per warp) ----
        float sf[4][4] = {};
        #pragma unroll
        for (int ks = 0; ks < 8; ks++) {
            const int kb = ks * 8;
            const int qrow = warp_m * 16 + lg;
            uint32_t a0 = Qs[qrow * 68 + kb + lt];
            uint32_t a1 = Qs[(qrow + 8) * 68 + kb + lt];
            uint32_t a2 = Qs[qrow * 68 + kb + lt + 4];
            uint32_t a3 = Qs[(qrow + 8) * 68 + kb + lt + 4];
            #pragma unroll
            for (int nt = 0; nt < 4; nt++) {
                int kvcol = warp_n * 32 + nt * 8 + lg;
                uint32_t b0 = Ks[kvcol * 68 + kb + lt];
                uint32_t b1 = Ks[kvcol * 68 + kb + lt + 4];
                mma8(sf[nt], a0, a1, a2, a3, b0, b1);
            }
        }
        {
            const int row = warp_m * 16 + lg;
            #pragma unroll
            for (int nt = 0; nt < 4; nt++) {
                int col = warp_n * 32 + nt * 8 + 2 * lt;
                Ss[row * 68 + col]           = sf[nt][0];
                Ss[row * 68 + col + 1]       = sf[nt][1];
                Ss[(row + 8) * 68 + col]     = sf[nt][2];
                Ss[(row + 8) * 68 + col + 1] = sf[nt][3];
            }
        }
        __syncthreads();

        // ---- online softmax: 4 lanes per row ----
        {
            const int row  = tid >> 2;
            const int part = tid & 3;
            float* srow = Ss + row * 68 + part;
            float mx = -1e30f;
            #pragma unroll
            for (int i = 0; i < 16; i++) mx = fmaxf(mx, srow[4 * i]);
            mx = fmaxf(mx, __shfl_xor_sync(0xffffffffu, mx, 1));
            mx = fmaxf(mx, __shfl_xor_sync(0xffffffffu, mx, 2));
            float mold = rowm[row];
            mx = fmaxf(mx, mold);
            float corr = __expf(mold - mx);
            float sum = 0.0f;
            #pragma unroll
            for (int i = 0; i < 16; i++) {
                float p = __expf(srow[4 * i] - mx);
                srow[4 * i] = __uint_as_float(f2tf(p));   // P as tf32 bits
                sum += p;
            }
            sum += __shfl_xor_sync(0xffffffffu, sum, 1);
            sum += __shfl_xor_sync(0xffffffffu, sum, 2);
            if (part == 0) {
                rowm[row] = mx;
                rowl[row] = rowl[row] * corr + sum;
                rowf[row] = corr;
            }
        }
        __syncthreads();

        // ---- O = O*corr + P @ V ----
        {
            const int qrow = warp_m * 16 + lg;
            float c0 = rowf[qrow];
            float c8 = rowf[qrow + 8];
            #pragma unroll
            for (int nt = 0; nt < 4; nt++) {
                o_acc[nt][0] *= c0; o_acc[nt][1] *= c0;
                o_acc[nt][2] *= c8; o_acc[nt][3] *= c8;
            }
            #pragma unroll
            for (int ks = 0; ks < 8; ks++) {
                const int kb = ks * 8;
                uint32_t a0 = __float_as_uint(Ss[qrow * 68 + kb + lt]);
                uint32_t a1 = __float_as_uint(Ss[(qrow + 8) * 68 + kb + lt]);
                uint32_t a2 = __float_as_uint(Ss[qrow * 68 + kb + lt + 4]);
                uint32_t a3 = __float_as_uint(Ss[(qrow + 8) * 68 + kb + lt + 4]);
                #pragma unroll
                for (int nt = 0; nt < 4; nt++) {
                    int dcol = warp_n * 32 + nt * 8 + lg;
                    uint32_t b0 = Vs[(kb + lt) * 68 + dcol];
                    uint32_t b1 = Vs[(kb + lt + 4) * 68 + dcol];
                    mma8(o_acc[nt], a0, a1, a2, a3, b0, b1);
                }
            }
        }
    }

    __syncthreads();
    {
        const int qrow = warp_m * 16 + lg;
        float inv0 = 1.0f / rowl[qrow];
        float inv8 = 1.0f / rowl[qrow + 8];
        #pragma unroll
        for (int nt = 0; nt < 4; nt++) {
            int col = warp_n * 32 + nt * 8 + 2 * lt;
            float2 lo = make_float2(__uint_as_float(f2tf(o_acc[nt][0] * inv0)),
                                    __uint_as_float(f2tf(o_acc[nt][1] * inv0)));
            float2 hi = make_float2(__uint_as_float(f2tf(o_acc[nt][2] * inv8)),
                                    __uint_as_float(f2tf(o_acc[nt][3] * inv8)));
            *(float2*)&g_O[((size_t)bn * HW + q0 + qrow)     * DHEAD + col] = lo;
            *(float2*)&g_O[((size_t)bn * HW + q0 + qrow + 8) * DHEAD + col] = hi;
        }
    }
}

// ---------------------------------------------------------------------------
// Kernel 3: output projection + head concat + NCHW transpose (tf32 mma).
// out[b][c][s] = bo[c] + sum_hd O[b][hd/64][s][hd%64] * Wo[c][hd]
// Tile 64(c) x 64(s), BK=32.
// ---------------------------------------------------------------------------
__global__ __launch_bounds__(256) void proj_kernel(
    const float* __restrict__ Wo, const float* __restrict__ bo,
    float* __restrict__ out)
{
    __shared__ uint32_t Ws_s[64 * 36];   // [c][kk]
    __shared__ uint32_t As_s[64 * 36];   // [s][kk]

    const int b  = blockIdx.z;
    const int c0 = blockIdx.y * 64;
    const int s0 = blockIdx.x * 64;
    const int tid    = threadIdx.x;
    const int wid    = tid >> 5;
    const int lane   = tid & 31;
    const int lg     = lane >> 2;
    const int lt     = lane & 3;
    const int warp_m = wid >> 1;   // c
    const int warp_n = wid & 1;    // s

    float acc[4][4] = {};

    for (int k0 = 0; k0 < C_DIM; k0 += 32) {
        const int n  = k0 >> 6;    // BK=32 never crosses head boundary
        const int d0 = k0 & 63;
        #pragma unroll
        for (int t = 0; t < 8; t++) {
            int idx = tid + t * 256;
            int sl = idx >> 5, kk = idx & 31;
            As_s[sl * 36 + kk] = __float_as_uint(
                g_O[((size_t)(b * HEADS + n) * HW + s0 + sl) * DHEAD + d0 + kk]);
        }
        #pragma unroll
        for (int t = 0; t < 8; t++) {
            int idx = tid + t * 256;
            int cl = idx >> 5, kk = idx & 31;
            Ws_s[cl * 36 + kk] = f2tf(Wo[(size_t)(c0 + cl) * C_DIM + k0 + kk]);
        }
        __syncthreads();

        #pragma unroll
        for (int ks = 0; ks < 4; ks++) {
            const int kb = ks * 8;
            const int crow = warp_m * 16 + lg;
            uint32_t a0 = Ws_s[crow * 36 + kb + lt];
            uint32_t a1 = Ws_s[(crow + 8) * 36 + kb + lt];
            uint32_t a2 = Ws_s[crow * 36 + kb + lt + 4];
            uint32_t a3 = Ws_s[(crow + 8) * 36 + kb + lt + 4];
            #pragma unroll
            for (int nt = 0; nt < 4; nt++) {
                int scol = warp_n * 32 + nt * 8 + lg;
                uint32_t b0 = As_s[scol * 36 + kb + lt];
                uint32_t b1 = As_s[scol * 36 + kb + lt + 4];
                mma8(acc[nt], a0, a1, a2, a3, b0, b1);
            }
        }
        __syncthreads();
    }

    const int crow = c0 + warp_m * 16 + lg;
    const float bias0 = bo[crow];
    const float bias8 = bo[crow + 8];
    #pragma unroll
    for (int nt = 0; nt < 4; nt++) {
        int s = s0 + warp_n * 32 + nt * 8 + 2 * lt;
        out[((size_t)b * C_DIM + crow)     * HW + s]     = acc[nt][0] + bias0;
        out[((size_t)b * C_DIM + crow)     * HW + s + 1] = acc[nt][1] + bias0;
        out[((size_t)b * C_DIM + crow + 8) * HW + s]     = acc[nt][2] + bias8;
        out[((size_t)b * C_DIM + crow + 8) * HW + s + 1] = acc[nt][3] + bias8;
    }
}

// ---------------------------------------------------------------------------
extern "C" void kernel_launch(void* const* d_in, const int* in_sizes, int n_in,
                              void* d_out, int out_size)
{
    const float* X  = (const float*)d_in[0];
    const float* Wq = (const float*)d_in[1];
    const float* bq = (const float*)d_in[2];
    const float* Wk = (const float*)d_in[3];
    const float* bk = (const float*)d_in[4];
    const float* Wv = (const float*)d_in[5];
    const float* bv = (const float*)d_in[6];
    const float* Wo = (const float*)d_in[7];
    const float* bo = (const float*)d_in[8];
    float* out = (float*)d_out;

    cudaFuncSetAttribute(attn_kernel,
                         cudaFuncAttributeMaxDynamicSharedMemorySize,
                         ATTN_SMEM_BYTES);

    qkv_kernel<<<dim3(HW / 64, BN, 3), 256>>>(X, Wq, bq, Wk, bk, Wv, bv);
    attn_kernel<<<dim3(HW / 64, BN), 256, ATTN_SMEM_BYTES>>>();
    proj_kernel<<<dim3(HW / 64, C_DIM / 64, BATCH), 256>>>(Wo, bo, out);
}

// round 3
// speedup vs baseline: 2.8412x; 1.1609x over previous
#include <cuda_runtime.h>
#include <math.h>
#include <stdint.h>

#define HEADS   8
#define DHEAD   64
#define C_DIM   512
#define BATCH   2
#define HW      2304          // 48*48
#define BN      (BATCH*HEADS) // 16
#define KCH     32            // kv chunk rows in attention
#define NCH     (HW / KCH)    // 72

// Scratch (no cudaMalloc allowed). Values are tf32-rounded fp32 bits.
__device__ float g_Q[BN * HW * DHEAD];
__device__ float g_K[BN * HW * DHEAD];
__device__ float g_V[BN * HW * DHEAD];
__device__ float g_O[BN * HW * DHEAD];

// ---------------------------------------------------------------------------
// helpers
// ---------------------------------------------------------------------------
__device__ __forceinline__ uint32_t f2tf(float x) {
    uint32_t u;
    asm("cvt.rna.tf32.f32 %0, %1;" : "=r"(u) : "f"(x));
    return u;
}

__device__ __forceinline__ void mma8(float* c,
                                     uint32_t a0, uint32_t a1, uint32_t a2, uint32_t a3,
                                     uint32_t b0, uint32_t b1) {
    asm volatile(
        "mma.sync.aligned.m16n8k8.row.col.f32.tf32.tf32.f32 "
        "{%0,%1,%2,%3}, {%4,%5,%6,%7}, {%8,%9}, {%0,%1,%2,%3};"
        : "+f"(c[0]), "+f"(c[1]), "+f"(c[2]), "+f"(c[3])
        : "r"(a0), "r"(a1), "r"(a2), "r"(a3), "r"(b0), "r"(b1));
}

__device__ __forceinline__ uint32_t smem_u32(const void* p) {
    return (uint32_t)__cvta_generic_to_shared(p);
}

__device__ __forceinline__ void cp16(uint32_t dst, const void* src) {
    asm volatile("cp.async.cg.shared.global [%0], [%1], 16;"
                 :: "r"(dst), "l"(src) : "memory");
}

// ---------------------------------------------------------------------------
// Kernel 1: merged QKV projection (tf32 mma). X tile loaded once for Q,K,V.
// Out[bn][s][d] = (sum_c X[b][c][s] * W[n][d][c] + b[n][d]) * (Q? 0.125 : 1)
// grid (36 s-tiles, 16 bn), block 256 (8 warps, 4x2), tile 64x64, BK=32.
// ---------------------------------------------------------------------------
__global__ __launch_bounds__(256) void qkv_kernel(
    const float* __restrict__ X,
    const float* __restrict__ Wq, const float* __restrict__ bq,
    const float* __restrict__ Wk, const float* __restrict__ bk,
    const float* __restrict__ Wv, const float* __restrict__ bv)
{
    __shared__ uint32_t Xs[32 * 68];        // [kk][sl]
    __shared__ uint32_t Ws[3][64 * 36];     // [qkv][d][kk]

    const int bn = blockIdx.y;
    const int b  = bn >> 3;
    const int n  = bn & 7;
    const int s0 = blockIdx.x * 64;

    const int tid    = threadIdx.x;
    const int wid    = tid >> 5;
    const int lane   = tid & 31;
    const int lg     = lane >> 2;
    const int lt     = lane & 3;
    const int warp_m = wid >> 1;      // s
    const int warp_n = wid & 1;       // d

    const float* Wp[3] = {Wq, Wk, Wv};
    const float* bp[3] = {bq, bk, bv};

    float acc[3][4][4] = {};

    for (int k0 = 0; k0 < C_DIM; k0 += 32) {
        // X tile: 32(k) x 64(s), 512 16B segments, 2 per thread
        #pragma unroll
        for (int t = 0; t < 2; t++) {
            int idx = tid + t * 256;
            int kk = idx >> 4, seg = idx & 15;
            const float4 v = *(const float4*)&X[((size_t)b * C_DIM + k0 + kk) * HW + s0 + seg * 4];
            uint32_t* d = &Xs[kk * 68 + seg * 4];
            d[0] = f2tf(v.x); d[1] = f2tf(v.y); d[2] = f2tf(v.z); d[3] = f2tf(v.w);
        }
        // W tiles: 3 x 64(d) x 32(k), 512 segs each, 2 per thread per array
        #pragma unroll
        for (int w = 0; w < 3; w++) {
            #pragma unroll
            for (int t = 0; t < 2; t++) {
                int idx = tid + t * 256;
                int d = idx >> 3, seg = idx & 7;
                const float4 v = *(const float4*)&Wp[w][((size_t)n * DHEAD + d) * C_DIM + k0 + seg * 4];
                uint32_t* ds = &Ws[w][d * 36 + seg * 4];
                ds[0] = f2tf(v.x); ds[1] = f2tf(v.y); ds[2] = f2tf(v.z); ds[3] = f2tf(v.w);
            }
        }
        __syncthreads();

        #pragma unroll
        for (int ks = 0; ks < 4; ks++) {
            const int kb = ks * 8;
            const int srow = warp_m * 16 + lg;
            uint32_t a0 = Xs[(kb + lt) * 68 + srow];
            uint32_t a1 = Xs[(kb + lt) * 68 + srow + 8];
            uint32_t a2 = Xs[(kb + lt + 4) * 68 + srow];
            uint32_t a3 = Xs[(kb + lt + 4) * 68 + srow + 8];
            #pragma unroll
            for (int w = 0; w < 3; w++) {
                #pragma unroll
                for (int nt = 0; nt < 4; nt++) {
                    int dcol = warp_n * 32 + nt * 8 + lg;
                    uint32_t b0 = Ws[w][dcol * 36 + kb + lt];
                    uint32_t b1 = Ws[w][dcol * 36 + kb + lt + 4];
                    mma8(acc[w][nt], a0, a1, a2, a3, b0, b1);
                }
            }
        }
        __syncthreads();
    }

    float* Outp[3] = {g_Q, g_K, g_V};
    const int row0 = s0 + warp_m * 16 + lg;
    #pragma unroll
    for (int w = 0; w < 3; w++) {
        const float scale = (w == 0) ? 0.125f : 1.0f;
        float* Out = Outp[w];
        #pragma unroll
        for (int nt = 0; nt < 4; nt++) {
            int col = warp_n * 32 + nt * 8 + 2 * lt;
            float b0f = bp[w][n * DHEAD + col];
            float b1f = bp[w][n * DHEAD + col + 1];
            float2 lo = make_float2(
                __uint_as_float(f2tf((acc[w][nt][0] + b0f) * scale)),
                __uint_as_float(f2tf((acc[w][nt][1] + b1f) * scale)));
            float2 hi = make_float2(
                __uint_as_float(f2tf((acc[w][nt][2] + b0f) * scale)),
                __uint_as_float(f2tf((acc[w][nt][3] + b1f) * scale)));
            *(float2*)&Out[((size_t)bn * HW + row0)     * DHEAD + col] = lo;
            *(float2*)&Out[((size_t)bn * HW + row0 + 8) * DHEAD + col] = hi;
        }
    }
}

// ---------------------------------------------------------------------------
// Kernel 2: flash attention, Q fragments register-resident, cp.async
// double-buffered 32-row K/V chunks, tf32 mma, fp32 online softmax.
// grid (36 q-tiles, 16 bn), block 256 (8 warps: 4 m x 2 n).
// ---------------------------------------------------------------------------
__global__ __launch_bounds__(256) void attn_kernel()
{
    __shared__ uint32_t Ks[2][KCH * 68];   // [buf][kv][d]
    __shared__ uint32_t Vs[2][KCH * 68];   // [buf][kv][d]
    __shared__ float    Ss[64 * 36];       // scores / P (tf32 bits)
    __shared__ float    rowm[64], rowl[64], rowf[64];

    const int bn = blockIdx.y;
    const int q0 = blockIdx.x * 64;
    const int tid    = threadIdx.x;
    const int wid    = tid >> 5;
    const int lane   = tid & 31;
    const int lg     = lane >> 2;
    const int lt     = lane & 3;
    const int warp_m = wid >> 1;
    const int warp_n = wid & 1;
    const int qrow   = warp_m * 16 + lg;

    // ---- Q fragments in registers (Q is pre-scaled by 1/8, tf32-rounded) ----
    uint32_t qa[8][4];
    {
        const size_t base = ((size_t)bn * HW + q0 + qrow) * DHEAD;
        #pragma unroll
        for (int ks = 0; ks < 8; ks++) {
            int col = ks * 8 + lt;
            qa[ks][0] = __float_as_uint(g_Q[base + col]);
            qa[ks][1] = __float_as_uint(g_Q[base + 8 * DHEAD + col]);
            qa[ks][2] = __float_as_uint(g_Q[base + col + 4]);
            qa[ks][3] = __float_as_uint(g_Q[base + 8 * DHEAD + col + 4]);
        }
    }
    if (tid < 64) { rowm[tid] = -1e30f; rowl[tid] = 0.0f; }

    // ---- prefetch chunk 0 into buffer 0 ----
    {
        #pragma unroll
        for (int t = 0; t < 4; t++) {
            int idx = tid + t * 256;
            int r = (idx >> 4) & 31, seg = idx & 15;
            const float* src = (idx < 512 ? g_K : g_V)
                             + ((size_t)bn * HW + r) * DHEAD + seg * 4;
            uint32_t dst = smem_u32(idx < 512 ? &Ks[0][r * 68 + seg * 4]
                                              : &Vs[0][r * 68 + seg * 4]);
            cp16(dst, src);
        }
        asm volatile("cp.async.commit_group;" ::: "memory");
    }

    float o_acc[4][4] = {};

    for (int kt = 0; kt < NCH; kt++) {
        const int buf = kt & 1;
        asm volatile("cp.async.wait_group 0;" ::: "memory");
        __syncthreads();   // chunk kt visible; prev iter fully done (buf^1 free)

        if (kt + 1 < NCH) {
            #pragma unroll
            for (int t = 0; t < 4; t++) {
                int idx = tid + t * 256;
                int r = (idx >> 4) & 31, seg = idx & 15;
                const float* src = (idx < 512 ? g_K : g_V)
                                 + ((size_t)bn * HW + (size_t)(kt + 1) * KCH + r) * DHEAD + seg * 4;
                uint32_t dst = smem_u32(idx < 512 ? &Ks[buf ^ 1][r * 68 + seg * 4]
                                                  : &Vs[buf ^ 1][r * 68 + seg * 4]);
                cp16(dst, src);
            }
            asm volatile("cp.async.commit_group;" ::: "memory");
        }

        // ---- S = Q @ K^T  (warp: m16 x n16) ----
        float sf[2][4] = {};
        #pragma unroll
        for (int ks = 0; ks < 8; ks++) {
            const int kb = ks * 8;
            #pragma unroll
            for (int nt = 0; nt < 2; nt++) {
                int kvcol = warp_n * 16 + nt * 8 + lg;
                uint32_t b0 = Ks[buf][kvcol * 68 + kb + lt];
                uint32_t b1 = Ks[buf][kvcol * 68 + kb + lt + 4];
                mma8(sf[nt], qa[ks][0], qa[ks][1], qa[ks][2], qa[ks][3], b0, b1);
            }
        }
        #pragma unroll
        for (int nt = 0; nt < 2; nt++) {
            int col = warp_n * 16 + nt * 8 + 2 * lt;
            *(float2*)&Ss[qrow * 36 + col]       = make_float2(sf[nt][0], sf[nt][1]);
            *(float2*)&Ss[(qrow + 8) * 36 + col] = make_float2(sf[nt][2], sf[nt][3]);
        }
        __syncthreads();

        // ---- online softmax over 32 cols (4 lanes / row) ----
        {
            const int row  = tid >> 2;
            const int part = tid & 3;
            float* srow = Ss + row * 36 + part;
            float mx = -1e30f;
            #pragma unroll
            for (int i = 0; i < 8; i++) mx = fmaxf(mx, srow[4 * i]);
            mx = fmaxf(mx, __shfl_xor_sync(0xffffffffu, mx, 1));
            mx = fmaxf(mx, __shfl_xor_sync(0xffffffffu, mx, 2));
            float mold = rowm[row];
            mx = fmaxf(mx, mold);
            float corr = __expf(mold - mx);
            float sum = 0.0f;
            #pragma unroll
            for (int i = 0; i < 8; i++) {
                float p = __expf(srow[4 * i] - mx);
                srow[4 * i] = __uint_as_float(f2tf(p));
                sum += p;
            }
            sum += __shfl_xor_sync(0xffffffffu, sum, 1);
            sum += __shfl_xor_sync(0xffffffffu, sum, 2);
            if (part == 0) {
                rowm[row] = mx;
                rowl[row] = rowl[row] * corr + sum;
                rowf[row] = corr;
            }
        }
        __syncthreads();

        // ---- O = O*corr + P @ V  (warp: m16 x n32, k=32) ----
        {
            float c0 = rowf[qrow];
            float c8 = rowf[qrow + 8];
            #pragma unroll
            for (int nt = 0; nt < 4; nt++) {
                o_acc[nt][0] *= c0; o_acc[nt][1] *= c0;
                o_acc[nt][2] *= c8; o_acc[nt][3] *= c8;
            }
            #pragma unroll
            for (int ks = 0; ks < 4; ks++) {
                const int kb = ks * 8;
                uint32_t a0 = __float_as_uint(Ss[qrow * 36 + kb + lt]);
                uint32_t a1 = __float_as_uint(Ss[(qrow + 8) * 36 + kb + lt]);
                uint32_t a2 = __float_as_uint(Ss[qrow * 36 + kb + lt + 4]);
                uint32_t a3 = __float_as_uint(Ss[(qrow + 8) * 36 + kb + lt + 4]);
                #pragma unroll
                for (int nt = 0; nt < 4; nt++) {
                    int dcol = warp_n * 32 + nt * 8 + lg;
                    uint32_t b0 = Vs[buf][(kb + lt) * 68 + dcol];
                    uint32_t b1 = Vs[buf][(kb + lt + 4) * 68 + dcol];
                    mma8(o_acc[nt], a0, a1, a2, a3, b0, b1);
                }
            }
        }
    }

    __syncthreads();
    {
        float inv0 = 1.0f / rowl[qrow];
        float inv8 = 1.0f / rowl[qrow + 8];
        #pragma unroll
        for (int nt = 0; nt < 4; nt++) {
            int col = warp_n * 32 + nt * 8 + 2 * lt;
            float2 lo = make_float2(__uint_as_float(f2tf(o_acc[nt][0] * inv0)),
                                    __uint_as_float(f2tf(o_acc[nt][1] * inv0)));
            float2 hi = make_float2(__uint_as_float(f2tf(o_acc[nt][2] * inv8)),
                                    __uint_as_float(f2tf(o_acc[nt][3] * inv8)));
            *(float2*)&g_O[((size_t)bn * HW + q0 + qrow)     * DHEAD + col] = lo;
            *(float2*)&g_O[((size_t)bn * HW + q0 + qrow + 8) * DHEAD + col] = hi;
        }
    }
}

// ---------------------------------------------------------------------------
// Kernel 3: output projection + head concat + NCHW transpose (tf32 mma).
// ---------------------------------------------------------------------------
__global__ __launch_bounds__(256) void proj_kernel(
    const float* __restrict__ Wo, const float* __restrict__ bo,
    float* __restrict__ out)
{
    __shared__ uint32_t Ws_s[64 * 36];   // [c][kk]
    __shared__ uint32_t As_s[64 * 36];   // [s][kk]

    const int b  = blockIdx.z;
    const int c0 = blockIdx.y * 64;
    const int s0 = blockIdx.x * 64;
    const int tid    = threadIdx.x;
    const int wid    = tid >> 5;
    const int lane   = tid & 31;
    const int lg     = lane >> 2;
    const int lt     = lane & 3;
    const int warp_m = wid >> 1;   // c
    const int warp_n = wid & 1;    // s

    float acc[4][4] = {};

    for (int k0 = 0; k0 < C_DIM; k0 += 32) {
        const int n  = k0 >> 6;
        const int d0 = k0 & 63;
        #pragma unroll
        for (int t = 0; t < 2; t++) {
            int idx = tid + t * 256;
            int sl = idx >> 3, seg = idx & 7;
            const float4 v = *(const float4*)
                &g_O[((size_t)(b * HEADS + n) * HW + s0 + sl) * DHEAD + d0 + seg * 4];
            uint32_t* d = &As_s[sl * 36 + seg * 4];
            d[0] = __float_as_uint(v.x); d[1] = __float_as_uint(v.y);
            d[2] = __float_as_uint(v.z); d[3] = __float_as_uint(v.w);
        }
        #pragma unroll
        for (int t = 0; t < 2; t++) {
            int idx = tid + t * 256;
            int cl = idx >> 3, seg = idx & 7;
            const float4 v = *(const float4*)&Wo[(size_t)(c0 + cl) * C_DIM + k0 + seg * 4];
            uint32_t* d = &Ws_s[cl * 36 + seg * 4];
            d[0] = f2tf(v.x); d[1] = f2tf(v.y); d[2] = f2tf(v.z); d[3] = f2tf(v.w);
        }
        __syncthreads();

        #pragma unroll
        for (int ks = 0; ks < 4; ks++) {
            const int kb = ks * 8;
            const int crow = warp_m * 16 + lg;
            uint32_t a0 = Ws_s[crow * 36 + kb + lt];
            uint32_t a1 = Ws_s[(crow + 8) * 36 + kb + lt];
            uint32_t a2 = Ws_s[crow * 36 + kb + lt + 4];
            uint32_t a3 = Ws_s[(crow + 8) * 36 + kb + lt + 4];
            #pragma unroll
            for (int nt = 0; nt < 4; nt++) {
                int scol = warp_n * 32 + nt * 8 + lg;
                uint32_t b0 = As_s[scol * 36 + kb + lt];
                uint32_t b1 = As_s[scol * 36 + kb + lt + 4];
                mma8(acc[nt], a0, a1, a2, a3, b0, b1);
            }
        }
        __syncthreads();
    }

    const int crow = c0 + warp_m * 16 + lg;
    const float bias0 = bo[crow];
    const float bias8 = bo[crow + 8];
    #pragma unroll
    for (int nt = 0; nt < 4; nt++) {
        int s = s0 + warp_n * 32 + nt * 8 + 2 * lt;
        *(float2*)&out[((size_t)b * C_DIM + crow) * HW + s] =
            make_float2(acc[nt][0] + bias0, acc[nt][1] + bias0);
        *(float2*)&out[((size_t)b * C_DIM + crow + 8) * HW + s] =
            make_float2(acc[nt][2] + bias8, acc[nt][3] + bias8);
    }
}

// ---------------------------------------------------------------------------
extern "C" void kernel_launch(void* const* d_in, const int* in_sizes, int n_in,
                              void* d_out, int out_size)
{
    const float* X  = (const float*)d_in[0];
    const float* Wq = (const float*)d_in[1];
    const float* bq = (const float*)d_in[2];
    const float* Wk = (const float*)d_in[3];
    const float* bk = (const float*)d_in[4];
    const float* Wv = (const float*)d_in[5];
    const float* bv = (const float*)d_in[6];
    const float* Wo = (const float*)d_in[7];
    const float* bo = (const float*)d_in[8];
    float* out = (float*)d_out;

    qkv_kernel<<<dim3(HW / 64, BN), 256>>>(X, Wq, bq, Wk, bk, Wv, bv);
    attn_kernel<<<dim3(HW / 64, BN), 256>>>();
    proj_kernel<<<dim3(HW / 64, C_DIM / 64, BATCH), 256>>>(Wo, bo, out);
}

// round 4
// speedup vs baseline: 3.5678x; 1.2557x over previous
#include <cuda_runtime.h>
#include <math.h>
#include <stdint.h>

#define HEADS   8
#define DHEAD   64
#define C_DIM   512
#define BATCH   2
#define HW      2304          // 48*48
#define BN      (BATCH*HEADS) // 16
#define KCH     32            // kv chunk rows in attention
#define NCH     (HW / KCH)    // 72
#define QT      128           // q-tile rows in attention

// Scratch (no cudaMalloc allowed). All hold tf32-rounded fp32 bit patterns.
__device__ float g_Q[BN * HW * DHEAD];
__device__ float g_K[BN * HW * DHEAD];
__device__ float g_V[BN * HW * DHEAD];
__device__ float g_O[BN * HW * DHEAD];
__device__ float g_Xt[BATCH * C_DIM * HW];          // pre-converted X
__device__ float g_Wt[3 * HEADS * DHEAD * C_DIM];   // pre-converted Wq|Wk|Wv
__device__ float g_Wot[C_DIM * C_DIM];              // pre-converted Wo

#define NX  (BATCH * C_DIM * HW)          // 2359296
#define NW  (HEADS * DHEAD * C_DIM)       // 262144
#define NWO (C_DIM * C_DIM)               // 262144
#define NCVT (NX + 3 * NW + NWO)          // 3407872

// ---------------------------------------------------------------------------
// helpers
// ---------------------------------------------------------------------------
__device__ __forceinline__ uint32_t f2tf(float x) {
    uint32_t u;
    asm("cvt.rna.tf32.f32 %0, %1;" : "=r"(u) : "f"(x));
    return u;
}

__device__ __forceinline__ void mma8(float* c,
                                     uint32_t a0, uint32_t a1, uint32_t a2, uint32_t a3,
                                     uint32_t b0, uint32_t b1) {
    asm volatile(
        "mma.sync.aligned.m16n8k8.row.col.f32.tf32.tf32.f32 "
        "{%0,%1,%2,%3}, {%4,%5,%6,%7}, {%8,%9}, {%0,%1,%2,%3};"
        : "+f"(c[0]), "+f"(c[1]), "+f"(c[2]), "+f"(c[3])
        : "r"(a0), "r"(a1), "r"(a2), "r"(a3), "r"(b0), "r"(b1));
}

__device__ __forceinline__ uint32_t smem_u32(const void* p) {
    return (uint32_t)__cvta_generic_to_shared(p);
}

__device__ __forceinline__ void cp16(uint32_t dst, const void* src) {
    asm volatile("cp.async.cg.shared.global [%0], [%1], 16;"
                 :: "r"(dst), "l"(src) : "memory");
}
#define CP_COMMIT() asm volatile("cp.async.commit_group;" ::: "memory")
#define CP_WAIT0()  asm volatile("cp.async.wait_group 0;" ::: "memory")

// ---------------------------------------------------------------------------
// Kernel 0: one-time tf32 pre-conversion of X, Wq, Wk, Wv, Wo.
// ---------------------------------------------------------------------------
__global__ __launch_bounds__(256) void cvt_kernel(
    const float* __restrict__ X,
    const float* __restrict__ Wq, const float* __restrict__ Wk,
    const float* __restrict__ Wv, const float* __restrict__ Wo)
{
    int i = blockIdx.x * 256 + threadIdx.x;
    if (i >= NCVT) return;
    if (i < NX) {
        g_Xt[i] = __uint_as_float(f2tf(X[i]));
    } else if (i < NX + NW) {
        int j = i - NX;          g_Wt[j]          = __uint_as_float(f2tf(Wq[j]));
    } else if (i < NX + 2 * NW) {
        int j = i - NX - NW;     g_Wt[NW + j]     = __uint_as_float(f2tf(Wk[j]));
    } else if (i < NX + 3 * NW) {
        int j = i - NX - 2 * NW; g_Wt[2 * NW + j] = __uint_as_float(f2tf(Wv[j]));
    } else {
        int j = i - NX - 3 * NW; g_Wot[j]         = __uint_as_float(f2tf(Wo[j]));
    }
}

// ---------------------------------------------------------------------------
// Kernel 1: merged QKV projection, pre-converted inputs, cp.async double-buffer.
// grid (36 s-tiles, 16 bn), block 256 (8 warps 4m x 2n), tile 64x64, BK=32.
// ---------------------------------------------------------------------------
__global__ __launch_bounds__(256, 2) void qkv_kernel(
    const float* __restrict__ bq, const float* __restrict__ bk,
    const float* __restrict__ bv)
{
    __shared__ uint32_t Xs[2][32 * 68];        // [buf][kk][sl]
    __shared__ uint32_t Ws[2][3][64 * 36];     // [buf][qkv][d][kk]

    const int bn = blockIdx.y;
    const int b  = bn >> 3;
    const int n  = bn & 7;
    const int s0 = blockIdx.x * 64;

    const int tid    = threadIdx.x;
    const int wid    = tid >> 5;
    const int lane   = tid & 31;
    const int lg     = lane >> 2;
    const int lt     = lane & 3;
    const int warp_m = wid >> 1;
    const int warp_n = wid & 1;

    // per-thread load slots (computed once)
    // X: 512 segs of 16B -> 2/thread ; W: 1536 segs -> 6/thread
    const int xi  = tid;               // seg ids tid, tid+256
    float acc[3][4][4] = {};

    // prefetch chunk 0
    {
        #pragma unroll
        for (int t = 0; t < 2; t++) {
            int idx = xi + t * 256;
            int kk = idx >> 4, seg = idx & 15;
            cp16(smem_u32(&Xs[0][kk * 68 + seg * 4]),
                 &g_Xt[((size_t)b * C_DIM + kk) * HW + s0 + seg * 4]);
        }
        #pragma unroll
        for (int t = 0; t < 6; t++) {
            int idx = tid + t * 256;
            int w = idx >> 9, rem = idx & 511;
            int d = rem >> 3, seg = rem & 7;
            cp16(smem_u32(&Ws[0][w][d * 36 + seg * 4]),
                 &g_Wt[(size_t)w * NW + ((size_t)n * DHEAD + d) * C_DIM + seg * 4]);
        }
        CP_COMMIT();
    }

    for (int kc = 0; kc < C_DIM / 32; kc++) {
        const int buf = kc & 1;
        CP_WAIT0();
        __syncthreads();

        if (kc + 1 < C_DIM / 32) {
            const int k0 = (kc + 1) * 32;
            #pragma unroll
            for (int t = 0; t < 2; t++) {
                int idx = xi + t * 256;
                int kk = idx >> 4, seg = idx & 15;
                cp16(smem_u32(&Xs[buf ^ 1][kk * 68 + seg * 4]),
                     &g_Xt[((size_t)b * C_DIM + k0 + kk) * HW + s0 + seg * 4]);
            }
            #pragma unroll
            for (int t = 0; t < 6; t++) {
                int idx = tid + t * 256;
                int w = idx >> 9, rem = idx & 511;
                int d = rem >> 3, seg = rem & 7;
                cp16(smem_u32(&Ws[buf ^ 1][w][d * 36 + seg * 4]),
                     &g_Wt[(size_t)w * NW + ((size_t)n * DHEAD + d) * C_DIM + k0 + seg * 4]);
            }
            CP_COMMIT();
        }

        #pragma unroll
        for (int ks = 0; ks < 4; ks++) {
            const int kb = ks * 8;
            const int srow = warp_m * 16 + lg;
            uint32_t a0 = Xs[buf][(kb + lt) * 68 + srow];
            uint32_t a1 = Xs[buf][(kb + lt) * 68 + srow + 8];
            uint32_t a2 = Xs[buf][(kb + lt + 4) * 68 + srow];
            uint32_t a3 = Xs[buf][(kb + lt + 4) * 68 + srow + 8];
            #pragma unroll
            for (int w = 0; w < 3; w++) {
                #pragma unroll
                for (int nt = 0; nt < 4; nt++) {
                    int dcol = warp_n * 32 + nt * 8 + lg;
                    uint32_t b0 = Ws[buf][w][dcol * 36 + kb + lt];
                    uint32_t b1 = Ws[buf][w][dcol * 36 + kb + lt + 4];
                    mma8(acc[w][nt], a0, a1, a2, a3, b0, b1);
                }
            }
        }
    }

    const float* bp[3] = {bq, bk, bv};
    float* Outp[3] = {g_Q, g_K, g_V};
    const int row0 = s0 + warp_m * 16 + lg;
    #pragma unroll
    for (int w = 0; w < 3; w++) {
        const float scale = (w == 0) ? 0.125f : 1.0f;
        float* Out = Outp[w];
        #pragma unroll
        for (int nt = 0; nt < 4; nt++) {
            int col = warp_n * 32 + nt * 8 + 2 * lt;
            float b0f = bp[w][n * DHEAD + col];
            float b1f = bp[w][n * DHEAD + col + 1];
            float2 lo = make_float2(
                __uint_as_float(f2tf((acc[w][nt][0] + b0f) * scale)),
                __uint_as_float(f2tf((acc[w][nt][1] + b1f) * scale)));
            float2 hi = make_float2(
                __uint_as_float(f2tf((acc[w][nt][2] + b0f) * scale)),
                __uint_as_float(f2tf((acc[w][nt][3] + b1f) * scale)));
            *(float2*)&Out[((size_t)bn * HW + row0)     * DHEAD + col] = lo;
            *(float2*)&Out[((size_t)bn * HW + row0 + 8) * DHEAD + col] = hi;
        }
    }
}

// ---------------------------------------------------------------------------
// Kernel 2: flash attention, warp-private rows: 8 warps x 16 rows = 128 q-tile.
// Register online softmax (shfl within 4-lane groups), 1 block sync per chunk.
// grid (18 q-tiles, 16 bn), block 256.
// ---------------------------------------------------------------------------
__global__ __launch_bounds__(256, 2) void attn_kernel()
{
    __shared__ uint32_t Ks[2][KCH * 68];       // [buf][kv][d]
    __shared__ uint32_t Vs[2][KCH * 68];       // [buf][kv][d]
    __shared__ uint32_t Ps[8][16 * 36];        // per-warp P staging

    const int bn = blockIdx.y;
    const int q0 = blockIdx.x * QT;
    const int tid  = threadIdx.x;
    const int wid  = tid >> 5;
    const int lane = tid & 31;
    const int lg   = lane >> 2;
    const int lt   = lane & 3;
    const int qrow = q0 + wid * 16 + lg;       // this lane's row (and +8)

    // ---- Q fragments register-resident (g_Q pre-scaled, tf32 bits) ----
    uint32_t qa[8][4];
    {
        const size_t base = ((size_t)bn * HW + qrow) * DHEAD;
        #pragma unroll
        for (int ks = 0; ks < 8; ks++) {
            int col = ks * 8 + lt;
            qa[ks][0] = __float_as_uint(g_Q[base + col]);
            qa[ks][1] = __float_as_uint(g_Q[base + 8 * DHEAD + col]);
            qa[ks][2] = __float_as_uint(g_Q[base + col + 4]);
            qa[ks][3] = __float_as_uint(g_Q[base + 8 * DHEAD + col + 4]);
        }
    }

    // prefetch chunk 0
    {
        #pragma unroll
        for (int t = 0; t < 4; t++) {
            int idx = tid + t * 256;
            int r = (idx >> 4) & 31, seg = idx & 15;
            const float* src = (idx < 512 ? g_K : g_V)
                             + ((size_t)bn * HW + r) * DHEAD + seg * 4;
            cp16(smem_u32(idx < 512 ? &Ks[0][r * 68 + seg * 4]
                                    : &Vs[0][r * 68 + seg * 4]), src);
        }
        CP_COMMIT();
    }

    float o_acc[8][4] = {};
    float m0 = -1e30f, m8 = -1e30f, l0 = 0.0f, l8 = 0.0f;

    for (int kt = 0; kt < NCH; kt++) {
        const int buf = kt & 1;
        CP_WAIT0();
        __syncthreads();                        // only block sync per chunk

        if (kt + 1 < NCH) {
            #pragma unroll
            for (int t = 0; t < 4; t++) {
                int idx = tid + t * 256;
                int r = (idx >> 4) & 31, seg = idx & 15;
                const float* src = (idx < 512 ? g_K : g_V)
                                 + ((size_t)bn * HW + (size_t)(kt + 1) * KCH + r) * DHEAD + seg * 4;
                cp16(smem_u32(idx < 512 ? &Ks[buf ^ 1][r * 68 + seg * 4]
                                        : &Vs[buf ^ 1][r * 68 + seg * 4]), src);
            }
            CP_COMMIT();
        }

        // ---- S = Q @ K^T : warp-private m16 x n32 ----
        float sf[4][4] = {};
        #pragma unroll
        for (int ks = 0; ks < 8; ks++) {
            const int kb = ks * 8;
            #pragma unroll
            for (int nt = 0; nt < 4; nt++) {
                int kvcol = nt * 8 + lg;
                uint32_t b0 = Ks[buf][kvcol * 68 + kb + lt];
                uint32_t b1 = Ks[buf][kvcol * 68 + kb + lt + 4];
                mma8(sf[nt], qa[ks][0], qa[ks][1], qa[ks][2], qa[ks][3], b0, b1);
            }
        }

        // ---- register online softmax (rows lg and lg+8) ----
        float mx0 = -1e30f, mx8 = -1e30f;
        #pragma unroll
        for (int nt = 0; nt < 4; nt++) {
            mx0 = fmaxf(mx0, fmaxf(sf[nt][0], sf[nt][1]));
            mx8 = fmaxf(mx8, fmaxf(sf[nt][2], sf[nt][3]));
        }
        mx0 = fmaxf(mx0, __shfl_xor_sync(0xffffffffu, mx0, 1));
        mx0 = fmaxf(mx0, __shfl_xor_sync(0xffffffffu, mx0, 2));
        mx8 = fmaxf(mx8, __shfl_xor_sync(0xffffffffu, mx8, 1));
        mx8 = fmaxf(mx8, __shfl_xor_sync(0xffffffffu, mx8, 2));
        mx0 = fmaxf(mx0, m0);
        mx8 = fmaxf(mx8, m8);
        float corr0 = __expf(m0 - mx0);
        float corr8 = __expf(m8 - mx8);
        float sum0 = 0.0f, sum8 = 0.0f;
        #pragma unroll
        for (int nt = 0; nt < 4; nt++) {
            float p0 = __expf(sf[nt][0] - mx0);
            float p1 = __expf(sf[nt][1] - mx0);
            float p2 = __expf(sf[nt][2] - mx8);
            float p3 = __expf(sf[nt][3] - mx8);
            sum0 += p0 + p1;
            sum8 += p2 + p3;
            sf[nt][0] = p0; sf[nt][1] = p1; sf[nt][2] = p2; sf[nt][3] = p3;
        }
        sum0 += __shfl_xor_sync(0xffffffffu, sum0, 1);
        sum0 += __shfl_xor_sync(0xffffffffu, sum0, 2);
        sum8 += __shfl_xor_sync(0xffffffffu, sum8, 1);
        sum8 += __shfl_xor_sync(0xffffffffu, sum8, 2);
        m0 = mx0; m8 = mx8;
        l0 = l0 * corr0 + sum0;
        l8 = l8 * corr8 + sum8;

        // ---- stage P (C-frag -> A-frag reshape), warp-local ----
        uint32_t* P = Ps[wid];
        #pragma unroll
        for (int nt = 0; nt < 4; nt++) {
            int col = nt * 8 + 2 * lt;
            P[lg * 36 + col]           = f2tf(sf[nt][0]);
            P[lg * 36 + col + 1]       = f2tf(sf[nt][1]);
            P[(lg + 8) * 36 + col]     = f2tf(sf[nt][2]);
            P[(lg + 8) * 36 + col + 1] = f2tf(sf[nt][3]);
        }
        __syncwarp();

        // ---- O = O*corr + P @ V : warp-private m16 x n64, k=32 ----
        #pragma unroll
        for (int nt = 0; nt < 8; nt++) {
            o_acc[nt][0] *= corr0; o_acc[nt][1] *= corr0;
            o_acc[nt][2] *= corr8; o_acc[nt][3] *= corr8;
        }
        #pragma unroll
        for (int ks = 0; ks < 4; ks++) {
            const int kb = ks * 8;
            uint32_t a0 = P[lg * 36 + kb + lt];
            uint32_t a1 = P[(lg + 8) * 36 + kb + lt];
            uint32_t a2 = P[lg * 36 + kb + lt + 4];
            uint32_t a3 = P[(lg + 8) * 36 + kb + lt + 4];
            #pragma unroll
            for (int nt = 0; nt < 8; nt++) {
                int dcol = nt * 8 + lg;
                uint32_t b0 = Vs[buf][(kb + lt) * 68 + dcol];
                uint32_t b1 = Vs[buf][(kb + lt + 4) * 68 + dcol];
                mma8(o_acc[nt], a0, a1, a2, a3, b0, b1);
            }
        }
        __syncwarp();   // P reads done before next chunk overwrites
    }

    // ---- epilogue ----
    {
        float inv0 = 1.0f / l0;
        float inv8 = 1.0f / l8;
        #pragma unroll
        for (int nt = 0; nt < 8; nt++) {
            int col = nt * 8 + 2 * lt;
            float2 lo = make_float2(__uint_as_float(f2tf(o_acc[nt][0] * inv0)),
                                    __uint_as_float(f2tf(o_acc[nt][1] * inv0)));
            float2 hi = make_float2(__uint_as_float(f2tf(o_acc[nt][2] * inv8)),
                                    __uint_as_float(f2tf(o_acc[nt][3] * inv8)));
            *(float2*)&g_O[((size_t)bn * HW + qrow)     * DHEAD + col] = lo;
            *(float2*)&g_O[((size_t)bn * HW + qrow + 8) * DHEAD + col] = hi;
        }
    }
}

// ---------------------------------------------------------------------------
// Kernel 3: output projection + head concat + NCHW transpose (pre-converted Wo).
// ---------------------------------------------------------------------------
__global__ __launch_bounds__(256, 2) void proj_kernel(
    const float* __restrict__ bo, float* __restrict__ out)
{
    __shared__ uint32_t Ws_s[2][64 * 36];   // [buf][c][kk]
    __shared__ uint32_t As_s[2][64 * 36];   // [buf][s][kk]

    const int b  = blockIdx.z;
    const int c0 = blockIdx.y * 64;
    const int s0 = blockIdx.x * 64;
    const int tid    = threadIdx.x;
    const int wid    = tid >> 5;
    const int lane   = tid & 31;
    const int lg     = lane >> 2;
    const int lt     = lane & 3;
    const int warp_m = wid >> 1;   // c
    const int warp_n = wid & 1;    // s

    float acc[4][4] = {};

    // prefetch k-chunk 0
    {
        #pragma unroll
        for (int t = 0; t < 2; t++) {
            int idx = tid + t * 256;
            int sl = idx >> 3, seg = idx & 7;
            cp16(smem_u32(&As_s[0][sl * 36 + seg * 4]),
                 &g_O[((size_t)(b * HEADS) * HW + s0 + sl) * DHEAD + seg * 4]);
        }
        #pragma unroll
        for (int t = 0; t < 2; t++) {
            int idx = tid + t * 256;
            int cl = idx >> 3, seg = idx & 7;
            cp16(smem_u32(&Ws_s[0][cl * 36 + seg * 4]),
                 &g_Wot[(size_t)(c0 + cl) * C_DIM + seg * 4]);
        }
        CP_COMMIT();
    }

    for (int kc = 0; kc < C_DIM / 32; kc++) {
        const int buf = kc & 1;
        CP_WAIT0();
        __syncthreads();

        if (kc + 1 < C_DIM / 32) {
            const int k0 = (kc + 1) * 32;
            const int n  = k0 >> 6;
            const int d0 = k0 & 63;
            #pragma unroll
            for (int t = 0; t < 2; t++) {
                int idx = tid + t * 256;
                int sl = idx >> 3, seg = idx & 7;
                cp16(smem_u32(&As_s[buf ^ 1][sl * 36 + seg * 4]),
                     &g_O[((size_t)(b * HEADS + n) * HW + s0 + sl) * DHEAD + d0 + seg * 4]);
            }
            #pragma unroll
            for (int t = 0; t < 2; t++) {
                int idx = tid + t * 256;
                int cl = idx >> 3, seg = idx & 7;
                cp16(smem_u32(&Ws_s[buf ^ 1][cl * 36 + seg * 4]),
                     &g_Wot[(size_t)(c0 + cl) * C_DIM + k0 + seg * 4]);
            }
            CP_COMMIT();
        }

        #pragma unroll
        for (int ks = 0; ks < 4; ks++) {
            const int kb = ks * 8;
            const int crow = warp_m * 16 + lg;
            uint32_t a0 = Ws_s[buf][crow * 36 + kb + lt];
            uint32_t a1 = Ws_s[buf][(crow + 8) * 36 + kb + lt];
            uint32_t a2 = Ws_s[buf][crow * 36 + kb + lt + 4];
            uint32_t a3 = Ws_s[buf][(crow + 8) * 36 + kb + lt + 4];
            #pragma unroll
            for (int nt = 0; nt < 4; nt++) {
                int scol = warp_n * 32 + nt * 8 + lg;
                uint32_t b0 = As_s[buf][scol * 36 + kb + lt];
                uint32_t b1 = As_s[buf][scol * 36 + kb + lt + 4];
                mma8(acc[nt], a0, a1, a2, a3, b0, b1);
            }
        }
    }

    const int crow = c0 + warp_m * 16 + lg;
    const float bias0 = bo[crow];
    const float bias8 = bo[crow + 8];
    #pragma unroll
    for (int nt = 0; nt < 4; nt++) {
        int s = s0 + warp_n * 32 + nt * 8 + 2 * lt;
        *(float2*)&out[((size_t)b * C_DIM + crow) * HW + s] =
            make_float2(acc[nt][0] + bias0, acc[nt][1] + bias0);
        *(float2*)&out[((size_t)b * C_DIM + crow + 8) * HW + s] =
            make_float2(acc[nt][2] + bias8, acc[nt][3] + bias8);
    }
}

// ---------------------------------------------------------------------------
extern "C" void kernel_launch(void* const* d_in, const int* in_sizes, int n_in,
                              void* d_out, int out_size)
{
    const float* X  = (const float*)d_in[0];
    const float* Wq = (const float*)d_in[1];
    const float* bq = (const float*)d_in[2];
    const float* Wk = (const float*)d_in[3];
    const float* bk = (const float*)d_in[4];
    const float* Wv = (const float*)d_in[5];
    const float* bv = (const float*)d_in[6];
    const float* Wo = (const float*)d_in[7];
    const float* bo = (const float*)d_in[8];
    float* out = (float*)d_out;

    cvt_kernel<<<(NCVT + 255) / 256, 256>>>(X, Wq, Wk, Wv, Wo);
    qkv_kernel<<<dim3(HW / 64, BN), 256>>>(bq, bk, bv);
    attn_kernel<<<dim3(HW / QT, BN), 256>>>();
    proj_kernel<<<dim3(HW / 64, C_DIM / 64, BATCH), 256>>>(bo, out);
}

// round 5
// speedup vs baseline: 7.1332x; 1.9994x over previous
#include <cuda_runtime.h>
#include <cuda_fp16.h>
#include <stdint.h>

#define HEADS   8
#define DHEAD   64
#define C_DIM   512
#define BATCH   2
#define HW      2304          // 48*48
#define BN      (BATCH*HEADS) // 16
#define KCH     32            // kv chunk rows in attention
#define NCH     (HW / KCH)    // 72
#define QT      128           // q-tile rows in attention

// Scratch (no cudaMalloc allowed). All fp16.
__device__ __align__(16) __half g_Q[BN * HW * DHEAD];
__device__ __align__(16) __half g_K[BN * HW * DHEAD];
__device__ __align__(16) __half g_V[BN * HW * DHEAD];
__device__ __align__(16) __half g_O[BN * HW * DHEAD];
__device__ __align__(16) __half g_Xt[BATCH * C_DIM * HW];         // X as fp16
__device__ __align__(16) __half g_Wt[3 * HEADS * DHEAD * C_DIM];  // Wq|Wk|Wv fp16
__device__ __align__(16) __half g_Wot[C_DIM * C_DIM];             // Wo fp16

#define NX   (BATCH * C_DIM * HW)        // 2359296
#define NW   (HEADS * DHEAD * C_DIM)     // 262144
#define NWO  (C_DIM * C_DIM)             // 262144
#define NCVT (NX + 3 * NW + NWO)

// ---------------------------------------------------------------------------
// helpers
// ---------------------------------------------------------------------------
__device__ __forceinline__ uint32_t pack2(float a, float b) {
    __half2 h = __floats2half2_rn(a, b);
    return *(uint32_t*)&h;
}

__device__ __forceinline__ void mma16(float* c, const uint32_t* a, const uint32_t* b) {
    asm volatile(
        "mma.sync.aligned.m16n8k16.row.col.f32.f16.f16.f32 "
        "{%0,%1,%2,%3}, {%4,%5,%6,%7}, {%8,%9}, {%0,%1,%2,%3};"
        : "+f"(c[0]), "+f"(c[1]), "+f"(c[2]), "+f"(c[3])
        : "r"(a[0]), "r"(a[1]), "r"(a[2]), "r"(a[3]), "r"(b[0]), "r"(b[1]));
}

__device__ __forceinline__ uint32_t su(const void* p) {
    return (uint32_t)__cvta_generic_to_shared(p);
}

__device__ __forceinline__ void ldmx4(uint32_t* r, uint32_t a) {
    asm volatile("ldmatrix.sync.aligned.m8n8.x4.shared.b16 {%0,%1,%2,%3}, [%4];"
                 : "=r"(r[0]), "=r"(r[1]), "=r"(r[2]), "=r"(r[3]) : "r"(a));
}
__device__ __forceinline__ void ldmx4t(uint32_t* r, uint32_t a) {
    asm volatile("ldmatrix.sync.aligned.m8n8.x4.trans.shared.b16 {%0,%1,%2,%3}, [%4];"
                 : "=r"(r[0]), "=r"(r[1]), "=r"(r[2]), "=r"(r[3]) : "r"(a));
}
__device__ __forceinline__ void ldmx2(uint32_t* r, uint32_t a) {
    asm volatile("ldmatrix.sync.aligned.m8n8.x2.shared.b16 {%0,%1}, [%2];"
                 : "=r"(r[0]), "=r"(r[1]) : "r"(a));
}
__device__ __forceinline__ void ldmx2t(uint32_t* r, uint32_t a) {
    asm volatile("ldmatrix.sync.aligned.m8n8.x2.trans.shared.b16 {%0,%1}, [%2];"
                 : "=r"(r[0]), "=r"(r[1]) : "r"(a));
}

__device__ __forceinline__ void cp16(uint32_t dst, const void* src) {
    asm volatile("cp.async.cg.shared.global [%0], [%1], 16;"
                 :: "r"(dst), "l"(src) : "memory");
}
#define CP_COMMIT() asm volatile("cp.async.commit_group;" ::: "memory")
#define CP_WAIT0()  asm volatile("cp.async.wait_group 0;" ::: "memory")

// ---------------------------------------------------------------------------
// Kernel 0: one-time fp16 conversion of X, Wq|Wk|Wv, Wo. 4 elems/thread.
// ---------------------------------------------------------------------------
__global__ __launch_bounds__(256) void cvt_kernel(
    const float* __restrict__ X,
    const float* __restrict__ Wq, const float* __restrict__ Wk,
    const float* __restrict__ Wv, const float* __restrict__ Wo)
{
    int i = (blockIdx.x * 256 + threadIdx.x) * 4;
    if (i >= NCVT) return;
    const float* src;
    __half* dst;
    int j;
    if (i < NX)               { src = X;  dst = g_Xt;           j = i; }
    else if (i < NX + NW)     { src = Wq; dst = g_Wt;           j = i - NX; }
    else if (i < NX + 2 * NW) { src = Wk; dst = g_Wt + NW;      j = i - NX - NW; }
    else if (i < NX + 3 * NW) { src = Wv; dst = g_Wt + 2 * NW;  j = i - NX - 2 * NW; }
    else                      { src = Wo; dst = g_Wot;          j = i - NX - 3 * NW; }
    float4 v = *(const float4*)&src[j];
    uint2 h = make_uint2(pack2(v.x, v.y), pack2(v.z, v.w));
    *(uint2*)&dst[j] = h;
}

// ---------------------------------------------------------------------------
// Kernel 1: merged QKV projection, fp16 mma + ldmatrix, cp.async double-buffer.
// grid (36 s-tiles, 16 bn), block 256 (8 warps 4m x 2n), tile 64x64, BK=32.
// ---------------------------------------------------------------------------
#define XS 72   // Xs row stride (halfs): 64 + 8 pad
#define WS 40   // W/A/P row stride (halfs): 32 + 8 pad

__global__ __launch_bounds__(256, 2) void qkv_kernel(
    const float* __restrict__ bq, const float* __restrict__ bk,
    const float* __restrict__ bv)
{
    __shared__ __half Xs[2][32 * XS];        // [buf][k][s]
    __shared__ __half Ws[2][3][64 * WS];     // [buf][qkv][d][k]

    const int bn = blockIdx.y;
    const int b  = bn >> 3;
    const int n  = bn & 7;
    const int s0 = blockIdx.x * 64;

    const int tid    = threadIdx.x;
    const int wid    = tid >> 5;
    const int lane   = tid & 31;
    const int lg     = lane >> 2;
    const int lt     = lane & 3;
    const int warp_m = wid >> 1;
    const int warp_n = wid & 1;
    const int l7     = lane & 7;
    const int l8     = (lane >> 3) & 1;
    const int l16    = lane >> 4;

    float acc[3][4][4] = {};

    // loader lambda: fills buf with k-chunk kc (32 rows of X, 32 cols of W)
    auto load_chunk = [&](int bufi, int k0) {
        // X: 32 rows x 64 halfs = 8 segs/row -> 256 segs, 1/thread
        {
            int kk = tid >> 3, seg = tid & 7;
            cp16(su(&Xs[bufi][kk * XS + seg * 8]),
                 &g_Xt[((size_t)b * C_DIM + k0 + kk) * HW + s0 + seg * 8]);
        }
        // W: 3 x 64 rows x 32 halfs = 4 segs/row -> 768 segs, 3/thread
        #pragma unroll
        for (int t = 0; t < 3; t++) {
            int idx = tid + t * 256;
            int w = idx >> 8, rem = idx & 255;
            int d = rem >> 2, seg = rem & 3;
            cp16(su(&Ws[bufi][w][d * WS + seg * 8]),
                 &g_Wt[(size_t)w * NW + ((size_t)n * DHEAD + d) * C_DIM + k0 + seg * 8]);
        }
        CP_COMMIT();
    };

    load_chunk(0, 0);

    for (int kc = 0; kc < C_DIM / 32; kc++) {
        const int buf = kc & 1;
        CP_WAIT0();
        __syncthreads();
        if (kc + 1 < C_DIM / 32) load_chunk(buf ^ 1, (kc + 1) * 32);

        #pragma unroll
        for (int ks = 0; ks < 2; ks++) {
            // A = X[s][k] via trans ldmatrix from Xs[k][s]
            uint32_t a[4];
            ldmx4t(a, su(&Xs[buf][(ks * 16 + l16 * 8 + l7) * XS
                                  + warp_m * 16 + l8 * 8]));
            #pragma unroll
            for (int w = 0; w < 3; w++) {
                #pragma unroll
                for (int nt = 0; nt < 4; nt++) {
                    uint32_t bfr[2];
                    ldmx2(bfr, su(&Ws[buf][w][(warp_n * 32 + nt * 8 + l7) * WS
                                              + ks * 16 + l8 * 8]));
                    mma16(acc[w][nt], a, bfr);
                }
            }
        }
    }

    const float* bp[3] = {bq, bk, bv};
    __half* Outp[3] = {g_Q, g_K, g_V};
    const int row0 = s0 + warp_m * 16 + lg;
    #pragma unroll
    for (int w = 0; w < 3; w++) {
        const float scale = (w == 0) ? 0.125f : 1.0f;  // 1/sqrt(64) folded into Q
        __half* Out = Outp[w];
        #pragma unroll
        for (int nt = 0; nt < 4; nt++) {
            int col = warp_n * 32 + nt * 8 + 2 * lt;
            float b0f = bp[w][n * DHEAD + col];
            float b1f = bp[w][n * DHEAD + col + 1];
            *(uint32_t*)&Out[((size_t)bn * HW + row0) * DHEAD + col] =
                pack2((acc[w][nt][0] + b0f) * scale, (acc[w][nt][1] + b1f) * scale);
            *(uint32_t*)&Out[((size_t)bn * HW + row0 + 8) * DHEAD + col] =
                pack2((acc[w][nt][2] + b0f) * scale, (acc[w][nt][3] + b1f) * scale);
        }
    }
}

// ---------------------------------------------------------------------------
// Kernel 2: flash attention, fp16 mma + ldmatrix, warp-private 16 rows,
// register online softmax, cp.async double-buffered 32-row K/V chunks.
// grid (18 q-tiles, 16 bn), block 256.
// ---------------------------------------------------------------------------
__global__ __launch_bounds__(256, 2) void attn_kernel()
{
    __shared__ __half Ks[2][KCH * XS];      // [buf][kv][d]
    __shared__ __half Vs[2][KCH * XS];      // [buf][kv][d]
    __shared__ __half Ps[8][16 * WS];       // per-warp P staging [m][kv]

    const int bn = blockIdx.y;
    const int q0 = blockIdx.x * QT;
    const int tid  = threadIdx.x;
    const int wid  = tid >> 5;
    const int lane = tid & 31;
    const int lg   = lane >> 2;
    const int lt   = lane & 3;
    const int l7   = lane & 7;
    const int l8   = (lane >> 3) & 1;
    const int l16  = lane >> 4;
    const int qrow = q0 + wid * 16 + lg;

    // ---- Q fragments register-resident (pre-scaled fp16) ----
    uint32_t qa[4][4];
    {
        const __half* Qb = &g_Q[((size_t)bn * HW + qrow) * DHEAD];
        #pragma unroll
        for (int ks = 0; ks < 4; ks++) {
            int k = ks * 16 + 2 * lt;
            qa[ks][0] = *(const uint32_t*)&Qb[k];
            qa[ks][1] = *(const uint32_t*)&Qb[8 * DHEAD + k];
            qa[ks][2] = *(const uint32_t*)&Qb[k + 8];
            qa[ks][3] = *(const uint32_t*)&Qb[8 * DHEAD + k + 8];
        }
    }

    auto load_chunk = [&](int bufi, int kt) {
        // K,V: 32 rows x 64 halfs = 8 segs/row -> 2*256 segs, 2/thread
        #pragma unroll
        for (int t = 0; t < 2; t++) {
            int idx = tid + t * 256;
            int r = (idx >> 3) & 31, seg = idx & 7;
            const __half* src = (idx < 256 ? g_K : g_V)
                              + ((size_t)bn * HW + (size_t)kt * KCH + r) * DHEAD + seg * 8;
            cp16(su(idx < 256 ? &Ks[bufi][r * XS + seg * 8]
                              : &Vs[bufi][r * XS + seg * 8]), src);
        }
        CP_COMMIT();
    };

    load_chunk(0, 0);

    float o_acc[8][4] = {};
    float m0 = -1e30f, m8 = -1e30f, l0 = 0.0f, l8v = 0.0f;

    for (int kt = 0; kt < NCH; kt++) {
        const int buf = kt & 1;
        CP_WAIT0();
        __syncthreads();
        if (kt + 1 < NCH) load_chunk(buf ^ 1, kt + 1);

        // ---- S = Q @ K^T : warp-private m16 x n32, k=64 ----
        float sf[4][4] = {};
        #pragma unroll
        for (int ks = 0; ks < 4; ks++) {
            #pragma unroll
            for (int nt = 0; nt < 4; nt++) {
                uint32_t bfr[2];
                ldmx2(bfr, su(&Ks[buf][(nt * 8 + l7) * XS + ks * 16 + l8 * 8]));
                mma16(sf[nt], qa[ks], bfr);
            }
        }

        // ---- register online softmax (rows lg and lg+8) ----
        float mx0 = -1e30f, mx8 = -1e30f;
        #pragma unroll
        for (int nt = 0; nt < 4; nt++) {
            mx0 = fmaxf(mx0, fmaxf(sf[nt][0], sf[nt][1]));
            mx8 = fmaxf(mx8, fmaxf(sf[nt][2], sf[nt][3]));
        }
        mx0 = fmaxf(mx0, __shfl_xor_sync(0xffffffffu, mx0, 1));
        mx0 = fmaxf(mx0, __shfl_xor_sync(0xffffffffu, mx0, 2));
        mx8 = fmaxf(mx8, __shfl_xor_sync(0xffffffffu, mx8, 1));
        mx8 = fmaxf(mx8, __shfl_xor_sync(0xffffffffu, mx8, 2));
        mx0 = fmaxf(mx0, m0);
        mx8 = fmaxf(mx8, m8);
        float corr0 = __expf(m0 - mx0);
        float corr8 = __expf(m8 - mx8);
        float sum0 = 0.0f, sum8 = 0.0f;
        __half* P = Ps[wid];
        #pragma unroll
        for (int nt = 0; nt < 4; nt++) {
            float p0 = __expf(sf[nt][0] - mx0);
            float p1 = __expf(sf[nt][1] - mx0);
            float p2 = __expf(sf[nt][2] - mx8);
            float p3 = __expf(sf[nt][3] - mx8);
            sum0 += p0 + p1;
            sum8 += p2 + p3;
            int col = nt * 8 + 2 * lt;
            *(uint32_t*)&P[lg * WS + col]       = pack2(p0, p1);
            *(uint32_t*)&P[(lg + 8) * WS + col] = pack2(p2, p3);
        }
        sum0 += __shfl_xor_sync(0xffffffffu, sum0, 1);
        sum0 += __shfl_xor_sync(0xffffffffu, sum0, 2);
        sum8 += __shfl_xor_sync(0xffffffffu, sum8, 1);
        sum8 += __shfl_xor_sync(0xffffffffu, sum8, 2);
        m0 = mx0; m8 = mx8;
        l0  = l0  * corr0 + sum0;
        l8v = l8v * corr8 + sum8;
        __syncwarp();

        // ---- O = O*corr + P @ V : warp-private m16 x n64, k=32 ----
        #pragma unroll
        for (int nt = 0; nt < 8; nt++) {
            o_acc[nt][0] *= corr0; o_acc[nt][1] *= corr0;
            o_acc[nt][2] *= corr8; o_acc[nt][3] *= corr8;
        }
        #pragma unroll
        for (int ks = 0; ks < 2; ks++) {
            uint32_t a[4];
            ldmx4(a, su(&P[(l8 * 8 + l7) * WS + ks * 16 + l16 * 8]));
            #pragma unroll
            for (int nt = 0; nt < 8; nt++) {
                uint32_t bfr[2];
                ldmx2t(bfr, su(&Vs[buf][(ks * 16 + l8 * 8 + l7) * XS + nt * 8]));
                mma16(o_acc[nt], a, bfr);
            }
        }
        __syncwarp();   // P reads done before next chunk overwrites
    }

    // ---- epilogue ----
    {
        float inv0 = 1.0f / l0;
        float inv8 = 1.0f / l8v;
        #pragma unroll
        for (int nt = 0; nt < 8; nt++) {
            int col = nt * 8 + 2 * lt;
            *(uint32_t*)&g_O[((size_t)bn * HW + qrow) * DHEAD + col] =
                pack2(o_acc[nt][0] * inv0, o_acc[nt][1] * inv0);
            *(uint32_t*)&g_O[((size_t)bn * HW + qrow + 8) * DHEAD + col] =
                pack2(o_acc[nt][2] * inv8, o_acc[nt][3] * inv8);
        }
    }
}

// ---------------------------------------------------------------------------
// Kernel 3: output projection + head concat + NCHW transpose (fp16 mma).
// grid (36 s, 8 c, 2 b), block 256, tile 64(c) x 64(s), BK=32.
// ---------------------------------------------------------------------------
__global__ __launch_bounds__(256, 2) void proj_kernel(
    const float* __restrict__ bo, float* __restrict__ out)
{
    __shared__ __half Ws_s[2][64 * WS];   // [buf][c][k]
    __shared__ __half As_s[2][64 * WS];   // [buf][s][k]

    const int b  = blockIdx.z;
    const int c0 = blockIdx.y * 64;
    const int s0 = blockIdx.x * 64;
    const int tid    = threadIdx.x;
    const int wid    = tid >> 5;
    const int lane   = tid & 31;
    const int lg     = lane >> 2;
    const int lt     = lane & 3;
    const int l7     = lane & 7;
    const int l8     = (lane >> 3) & 1;
    const int l16    = lane >> 4;
    const int warp_m = wid >> 1;   // c
    const int warp_n = wid & 1;    // s

    float acc[4][4] = {};

    auto load_chunk = [&](int bufi, int k0) {
        const int n  = k0 >> 6;
        const int d0 = k0 & 63;
        #pragma unroll
        for (int t = 0; t < 2; t++) {
            int idx = tid + t * 256;
            int r = (idx >> 2) & 63, seg = idx & 3;
            if (idx < 256) {
                cp16(su(&As_s[bufi][r * WS + seg * 8]),
                     &g_O[((size_t)(b * HEADS + n) * HW + s0 + r) * DHEAD + d0 + seg * 8]);
            } else {
                cp16(su(&Ws_s[bufi][r * WS + seg * 8]),
                     &g_Wot[(size_t)(c0 + r) * C_DIM + k0 + seg * 8]);
            }
        }
        CP_COMMIT();
    };

    load_chunk(0, 0);

    for (int kc = 0; kc < C_DIM / 32; kc++) {
        const int buf = kc & 1;
        CP_WAIT0();
        __syncthreads();
        if (kc + 1 < C_DIM / 32) load_chunk(buf ^ 1, (kc + 1) * 32);

        #pragma unroll
        for (int ks = 0; ks < 2; ks++) {
            uint32_t a[4];
            ldmx4(a, su(&Ws_s[buf][(warp_m * 16 + l8 * 8 + l7) * WS
                                   + ks * 16 + l16 * 8]));
            #pragma unroll
            for (int nt = 0; nt < 4; nt++) {
                uint32_t bfr[2];
                ldmx2(bfr, su(&As_s[buf][(warp_n * 32 + nt * 8 + l7) * WS
                                         + ks * 16 + l8 * 8]));
                mma16(acc[nt], a, bfr);
            }
        }
    }

    const int crow = c0 + warp_m * 16 + lg;
    const float bias0 = bo[crow];
    const float bias8 = bo[crow + 8];
    #pragma unroll
    for (int nt = 0; nt < 4; nt++) {
        int s = s0 + warp_n * 32 + nt * 8 + 2 * lt;
        *(float2*)&out[((size_t)b * C_DIM + crow) * HW + s] =
            make_float2(acc[nt][0] + bias0, acc[nt][1] + bias0);
        *(float2*)&out[((size_t)b * C_DIM + crow + 8) * HW + s] =
            make_float2(acc[nt][2] + bias8, acc[nt][3] + bias8);
    }
}

// ---------------------------------------------------------------------------
extern "C" void kernel_launch(void* const* d_in, const int* in_sizes, int n_in,
                              void* d_out, int out_size)
{
    const float* X  = (const float*)d_in[0];
    const float* Wq = (const float*)d_in[1];
    const float* bq = (const float*)d_in[2];
    const float* Wk = (const float*)d_in[3];
    const float* bk = (const float*)d_in[4];
    const float* Wv = (const float*)d_in[5];
    const float* bv = (const float*)d_in[6];
    const float* Wo = (const float*)d_in[7];
    const float* bo = (const float*)d_in[8];
    float* out = (float*)d_out;

    cvt_kernel<<<(NCVT / 4 + 255) / 256, 256>>>(X, Wq, Wk, Wv, Wo);
    qkv_kernel<<<dim3(HW / 64, BN), 256>>>(bq, bk, bv);
    attn_kernel<<<dim3(HW / QT, BN), 256>>>();
    proj_kernel<<<dim3(HW / 64, C_DIM / 64, BATCH), 256>>>(bo, out);
}

// round 6
// speedup vs baseline: 7.6105x; 1.0669x over previous
#include <cuda_runtime.h>
#include <cuda_fp16.h>
#include <stdint.h>

#define HEADS   8
#define DHEAD   64
#define C_DIM   512
#define BATCH   2
#define HW      2304          // 48*48
#define BN      (BATCH*HEADS) // 16
#define KCH     32            // kv chunk rows in attention
#define NCH     (HW / KCH)    // 72
#define QT      128           // q-tile rows in attention

// Scratch (no cudaMalloc allowed). All fp16.
__device__ __align__(16) __half g_Q[BN * HW * DHEAD];
__device__ __align__(16) __half g_K[BN * HW * DHEAD];
__device__ __align__(16) __half g_V[BN * HW * DHEAD];
__device__ __align__(16) __half g_O[BN * HW * DHEAD];
__device__ __align__(16) __half g_Xt[BATCH * C_DIM * HW];         // X as fp16
__device__ __align__(16) __half g_Wt[3 * HEADS * DHEAD * C_DIM];  // Wq|Wk|Wv fp16
__device__ __align__(16) __half g_Wot[C_DIM * C_DIM];             // Wo fp16

#define NX   (BATCH * C_DIM * HW)        // 2359296
#define NW   (HEADS * DHEAD * C_DIM)     // 262144
#define NWO  (C_DIM * C_DIM)             // 262144
#define NCVT (NX + 3 * NW + NWO)

// ---------------------------------------------------------------------------
// helpers
// ---------------------------------------------------------------------------
__device__ __forceinline__ uint32_t pack2(float a, float b) {
    __half2 h = __floats2half2_rn(a, b);
    return *(uint32_t*)&h;
}

__device__ __forceinline__ void mma16(float* c, const uint32_t* a, const uint32_t* b) {
    asm volatile(
        "mma.sync.aligned.m16n8k16.row.col.f32.f16.f16.f32 "
        "{%0,%1,%2,%3}, {%4,%5,%6,%7}, {%8,%9}, {%0,%1,%2,%3};"
        : "+f"(c[0]), "+f"(c[1]), "+f"(c[2]), "+f"(c[3])
        : "r"(a[0]), "r"(a[1]), "r"(a[2]), "r"(a[3]), "r"(b[0]), "r"(b[1]));
}

__device__ __forceinline__ uint32_t su(const void* p) {
    return (uint32_t)__cvta_generic_to_shared(p);
}

__device__ __forceinline__ void ldmx4(uint32_t* r, uint32_t a) {
    asm volatile("ldmatrix.sync.aligned.m8n8.x4.shared.b16 {%0,%1,%2,%3}, [%4];"
                 : "=r"(r[0]), "=r"(r[1]), "=r"(r[2]), "=r"(r[3]) : "r"(a));
}
__device__ __forceinline__ void ldmx4t(uint32_t* r, uint32_t a) {
    asm volatile("ldmatrix.sync.aligned.m8n8.x4.trans.shared.b16 {%0,%1,%2,%3}, [%4];"
                 : "=r"(r[0]), "=r"(r[1]), "=r"(r[2]), "=r"(r[3]) : "r"(a));
}
__device__ __forceinline__ void ldmx2(uint32_t* r, uint32_t a) {
    asm volatile("ldmatrix.sync.aligned.m8n8.x2.shared.b16 {%0,%1}, [%2];"
                 : "=r"(r[0]), "=r"(r[1]) : "r"(a));
}
__device__ __forceinline__ void ldmx2t(uint32_t* r, uint32_t a) {
    asm volatile("ldmatrix.sync.aligned.m8n8.x2.trans.shared.b16 {%0,%1}, [%2];"
                 : "=r"(r[0]), "=r"(r[1]) : "r"(a));
}

__device__ __forceinline__ void cp16(uint32_t dst, const void* src) {
    asm volatile("cp.async.cg.shared.global [%0], [%1], 16;"
                 :: "r"(dst), "l"(src) : "memory");
}
#define CP_COMMIT() asm volatile("cp.async.commit_group;" ::: "memory")
#define CP_WAIT1()  asm volatile("cp.async.wait_group 1;" ::: "memory")

// ---------------------------------------------------------------------------
// Kernel 0: one-time fp16 conversion of X, Wq|Wk|Wv, Wo. 8 elems/thread.
// ---------------------------------------------------------------------------
__global__ __launch_bounds__(256) void cvt_kernel(
    const float* __restrict__ X,
    const float* __restrict__ Wq, const float* __restrict__ Wk,
    const float* __restrict__ Wv, const float* __restrict__ Wo)
{
    int i = (blockIdx.x * 256 + threadIdx.x) * 8;
    if (i >= NCVT) return;
    const float* src;
    __half* dst;
    int j;
    if (i < NX)               { src = X;  dst = g_Xt;           j = i; }
    else if (i < NX + NW)     { src = Wq; dst = g_Wt;           j = i - NX; }
    else if (i < NX + 2 * NW) { src = Wk; dst = g_Wt + NW;      j = i - NX - NW; }
    else if (i < NX + 3 * NW) { src = Wv; dst = g_Wt + 2 * NW;  j = i - NX - 2 * NW; }
    else                      { src = Wo; dst = g_Wot;          j = i - NX - 3 * NW; }
    float4 v0 = *(const float4*)&src[j];
    float4 v1 = *(const float4*)&src[j + 4];
    uint4 h = make_uint4(pack2(v0.x, v0.y), pack2(v0.z, v0.w),
                         pack2(v1.x, v1.y), pack2(v1.z, v1.w));
    *(uint4*)&dst[j] = h;
}

// ---------------------------------------------------------------------------
// Kernel 1: merged QKV projection, fp16 mma + ldmatrix, 3-stage cp.async ring.
// grid (36 s-tiles, 16 bn), block 256 (8 warps 4m x 2n), tile 64x64, BK=32.
// ---------------------------------------------------------------------------
#define XS 72   // Xs row stride (halfs): 64 + 8 pad
#define WS 40   // W/A/P row stride (halfs): 32 + 8 pad
#define NKC (C_DIM / 32)   // 16 k-chunks

__global__ __launch_bounds__(256, 2) void qkv_kernel(
    const float* __restrict__ bq, const float* __restrict__ bk,
    const float* __restrict__ bv)
{
    __shared__ __half Xs[3][32 * XS];        // [stage][k][s]
    __shared__ __half Ws[3][3][64 * WS];     // [stage][qkv][d][k]

    const int bn = blockIdx.y;
    const int b  = bn >> 3;
    const int n  = bn & 7;
    const int s0 = blockIdx.x * 64;

    const int tid    = threadIdx.x;
    const int wid    = tid >> 5;
    const int lane   = tid & 31;
    const int lg     = lane >> 2;
    const int lt     = lane & 3;
    const int warp_m = wid >> 1;
    const int warp_n = wid & 1;
    const int l7     = lane & 7;
    const int l8     = (lane >> 3) & 1;
    const int l16    = lane >> 4;

    float acc[3][4][4] = {};

    // issue cp.asyncs for k-chunk k0 into stage st (no commit)
    auto load_chunk = [&](int st, int k0) {
        {
            int kk = tid >> 3, seg = tid & 7;
            cp16(su(&Xs[st][kk * XS + seg * 8]),
                 &g_Xt[((size_t)b * C_DIM + k0 + kk) * HW + s0 + seg * 8]);
        }
        #pragma unroll
        for (int t = 0; t < 3; t++) {
            int idx = tid + t * 256;
            int w = idx >> 8, rem = idx & 255;
            int d = rem >> 2, seg = rem & 3;
            cp16(su(&Ws[st][w][d * WS + seg * 8]),
                 &g_Wt[(size_t)w * NW + ((size_t)n * DHEAD + d) * C_DIM + k0 + seg * 8]);
        }
    };

    load_chunk(0, 0);  CP_COMMIT();
    load_chunk(1, 32); CP_COMMIT();

    for (int kc = 0; kc < NKC; kc++) {
        const int st = kc % 3;
        CP_WAIT1();          // group for chunk kc complete (kc+1 may pend)
        __syncthreads();
        if (kc + 2 < NKC) load_chunk((kc + 2) % 3, (kc + 2) * 32);
        CP_COMMIT();         // always commit (possibly empty) to keep counts fixed

        #pragma unroll
        for (int ks = 0; ks < 2; ks++) {
            uint32_t a[4];
            ldmx4t(a, su(&Xs[st][(ks * 16 + l16 * 8 + l7) * XS
                                 + warp_m * 16 + l8 * 8]));
            #pragma unroll
            for (int w = 0; w < 3; w++) {
                #pragma unroll
                for (int nt = 0; nt < 4; nt++) {
                    uint32_t bfr[2];
                    ldmx2(bfr, su(&Ws[st][w][(warp_n * 32 + nt * 8 + l7) * WS
                                             + ks * 16 + l8 * 8]));
                    mma16(acc[w][nt], a, bfr);
                }
            }
        }
    }

    const float* bp[3] = {bq, bk, bv};
    __half* Outp[3] = {g_Q, g_K, g_V};
    const int row0 = s0 + warp_m * 16 + lg;
    #pragma unroll
    for (int w = 0; w < 3; w++) {
        const float scale = (w == 0) ? 0.125f : 1.0f;  // 1/sqrt(64) folded into Q
        __half* Out = Outp[w];
        #pragma unroll
        for (int nt = 0; nt < 4; nt++) {
            int col = warp_n * 32 + nt * 8 + 2 * lt;
            float b0f = bp[w][n * DHEAD + col];
            float b1f = bp[w][n * DHEAD + col + 1];
            *(uint32_t*)&Out[((size_t)bn * HW + row0) * DHEAD + col] =
                pack2((acc[w][nt][0] + b0f) * scale, (acc[w][nt][1] + b1f) * scale);
            *(uint32_t*)&Out[((size_t)bn * HW + row0 + 8) * DHEAD + col] =
                pack2((acc[w][nt][2] + b0f) * scale, (acc[w][nt][3] + b1f) * scale);
        }
    }
}

// ---------------------------------------------------------------------------
// Kernel 2: flash attention, fp16 mma + ldmatrix, warp-private 16 rows,
// register online softmax, 3-stage cp.async ring over 32-row K/V chunks.
// grid (18 q-tiles, 16 bn), block 256.
// ---------------------------------------------------------------------------
__global__ __launch_bounds__(256, 2) void attn_kernel()
{
    __shared__ __half Ks[3][KCH * XS];      // [stage][kv][d]
    __shared__ __half Vs[3][KCH * XS];      // [stage][kv][d]
    __shared__ __half Ps[8][16 * WS];       // per-warp P staging [m][kv]

    const int bn = blockIdx.y;
    const int q0 = blockIdx.x * QT;
    const int tid  = threadIdx.x;
    const int wid  = tid >> 5;
    const int lane = tid & 31;
    const int lg   = lane >> 2;
    const int lt   = lane & 3;
    const int l7   = lane & 7;
    const int l8   = (lane >> 3) & 1;
    const int l16  = lane >> 4;
    const int qrow = q0 + wid * 16 + lg;

    // ---- Q fragments register-resident (pre-scaled fp16) ----
    uint32_t qa[4][4];
    {
        const __half* Qb = &g_Q[((size_t)bn * HW + qrow) * DHEAD];
        #pragma unroll
        for (int ks = 0; ks < 4; ks++) {
            int k = ks * 16 + 2 * lt;
            qa[ks][0] = *(const uint32_t*)&Qb[k];
            qa[ks][1] = *(const uint32_t*)&Qb[8 * DHEAD + k];
            qa[ks][2] = *(const uint32_t*)&Qb[k + 8];
            qa[ks][3] = *(const uint32_t*)&Qb[8 * DHEAD + k + 8];
        }
    }

    auto load_chunk = [&](int st, int kt) {
        #pragma unroll
        for (int t = 0; t < 2; t++) {
            int idx = tid + t * 256;
            int r = (idx >> 3) & 31, seg = idx & 7;
            const __half* src = (idx < 256 ? g_K : g_V)
                              + ((size_t)bn * HW + (size_t)kt * KCH + r) * DHEAD + seg * 8;
            cp16(su(idx < 256 ? &Ks[st][r * XS + seg * 8]
                              : &Vs[st][r * XS + seg * 8]), src);
        }
    };

    load_chunk(0, 0); CP_COMMIT();
    load_chunk(1, 1); CP_COMMIT();

    float o_acc[8][4] = {};
    float m0 = -1e30f, m8 = -1e30f, l0 = 0.0f, l8v = 0.0f;

    for (int kt = 0; kt < NCH; kt++) {
        const int st = kt % 3;
        CP_WAIT1();
        __syncthreads();
        if (kt + 2 < NCH) load_chunk((kt + 2) % 3, kt + 2);
        CP_COMMIT();

        // ---- S = Q @ K^T : warp-private m16 x n32, k=64 ----
        float sf[4][4] = {};
        #pragma unroll
        for (int ks = 0; ks < 4; ks++) {
            #pragma unroll
            for (int nt = 0; nt < 4; nt++) {
                uint32_t bfr[2];
                ldmx2(bfr, su(&Ks[st][(nt * 8 + l7) * XS + ks * 16 + l8 * 8]));
                mma16(sf[nt], qa[ks], bfr);
            }
        }

        // ---- register online softmax (rows lg and lg+8) ----
        float mx0 = -1e30f, mx8 = -1e30f;
        #pragma unroll
        for (int nt = 0; nt < 4; nt++) {
            mx0 = fmaxf(mx0, fmaxf(sf[nt][0], sf[nt][1]));
            mx8 = fmaxf(mx8, fmaxf(sf[nt][2], sf[nt][3]));
        }
        mx0 = fmaxf(mx0, __shfl_xor_sync(0xffffffffu, mx0, 1));
        mx0 = fmaxf(mx0, __shfl_xor_sync(0xffffffffu, mx0, 2));
        mx8 = fmaxf(mx8, __shfl_xor_sync(0xffffffffu, mx8, 1));
        mx8 = fmaxf(mx8, __shfl_xor_sync(0xffffffffu, mx8, 2));
        mx0 = fmaxf(mx0, m0);
        mx8 = fmaxf(mx8, m8);
        float corr0 = __expf(m0 - mx0);
        float corr8 = __expf(m8 - mx8);
        float sum0 = 0.0f, sum8 = 0.0f;
        __half* P = Ps[wid];
        #pragma unroll
        for (int nt = 0; nt < 4; nt++) {
            float p0 = __expf(sf[nt][0] - mx0);
            float p1 = __expf(sf[nt][1] - mx0);
            float p2 = __expf(sf[nt][2] - mx8);
            float p3 = __expf(sf[nt][3] - mx8);
            sum0 += p0 + p1;
            sum8 += p2 + p3;
            int col = nt * 8 + 2 * lt;
            *(uint32_t*)&P[lg * WS + col]       = pack2(p0, p1);
            *(uint32_t*)&P[(lg + 8) * WS + col] = pack2(p2, p3);
        }
        sum0 += __shfl_xor_sync(0xffffffffu, sum0, 1);
        sum0 += __shfl_xor_sync(0xffffffffu, sum0, 2);
        sum8 += __shfl_xor_sync(0xffffffffu, sum8, 1);
        sum8 += __shfl_xor_sync(0xffffffffu, sum8, 2);
        m0 = mx0; m8 = mx8;
        l0  = l0  * corr0 + sum0;
        l8v = l8v * corr8 + sum8;
        __syncwarp();

        // ---- O = O*corr + P @ V : warp-private m16 x n64, k=32 ----
        #pragma unroll
        for (int nt = 0; nt < 8; nt++) {
            o_acc[nt][0] *= corr0; o_acc[nt][1] *= corr0;
            o_acc[nt][2] *= corr8; o_acc[nt][3] *= corr8;
        }
        #pragma unroll
        for (int ks = 0; ks < 2; ks++) {
            uint32_t a[4];
            ldmx4(a, su(&P[(l8 * 8 + l7) * WS + ks * 16 + l16 * 8]));
            #pragma unroll
            for (int nt = 0; nt < 8; nt++) {
                uint32_t bfr[2];
                ldmx2t(bfr, su(&Vs[st][(ks * 16 + l8 * 8 + l7) * XS + nt * 8]));
                mma16(o_acc[nt], a, bfr);
            }
        }
        __syncwarp();   // P reads done before next chunk overwrites
    }

    // ---- epilogue ----
    {
        float inv0 = 1.0f / l0;
        float inv8 = 1.0f / l8v;
        #pragma unroll
        for (int nt = 0; nt < 8; nt++) {
            int col = nt * 8 + 2 * lt;
            *(uint32_t*)&g_O[((size_t)bn * HW + qrow) * DHEAD + col] =
                pack2(o_acc[nt][0] * inv0, o_acc[nt][1] * inv0);
            *(uint32_t*)&g_O[((size_t)bn * HW + qrow + 8) * DHEAD + col] =
                pack2(o_acc[nt][2] * inv8, o_acc[nt][3] * inv8);
        }
    }
}

// ---------------------------------------------------------------------------
// Kernel 3: output projection + head concat + NCHW transpose (fp16 mma).
// grid (36 s, 8 c, 2 b), block 256, tile 64(c) x 64(s), BK=32, 3-stage ring.
// ---------------------------------------------------------------------------
__global__ __launch_bounds__(256, 2) void proj_kernel(
    const float* __restrict__ bo, float* __restrict__ out)
{
    __shared__ __half Ws_s[3][64 * WS];   // [stage][c][k]
    __shared__ __half As_s[3][64 * WS];   // [stage][s][k]

    const int b  = blockIdx.z;
    const int c0 = blockIdx.y * 64;
    const int s0 = blockIdx.x * 64;
    const int tid    = threadIdx.x;
    const int wid    = tid >> 5;
    const int lane   = tid & 31;
    const int lg     = lane >> 2;
    const int lt     = lane & 3;
    const int l7     = lane & 7;
    const int l8     = (lane >> 3) & 1;
    const int l16    = lane >> 4;
    const int warp_m = wid >> 1;   // c
    const int warp_n = wid & 1;    // s

    float acc[4][4] = {};

    auto load_chunk = [&](int st, int k0) {
        const int n  = k0 >> 6;
        const int d0 = k0 & 63;
        #pragma unroll
        for (int t = 0; t < 2; t++) {
            int idx = tid + t * 256;
            int r = (idx >> 2) & 63, seg = idx & 3;
            if (idx < 256) {
                cp16(su(&As_s[st][r * WS + seg * 8]),
                     &g_O[((size_t)(b * HEADS + n) * HW + s0 + r) * DHEAD + d0 + seg * 8]);
            } else {
                cp16(su(&Ws_s[st][r * WS + seg * 8]),
                     &g_Wot[(size_t)(c0 + r) * C_DIM + k0 + seg * 8]);
            }
        }
    };

    load_chunk(0, 0);  CP_COMMIT();
    load_chunk(1, 32); CP_COMMIT();

    for (int kc = 0; kc < NKC; kc++) {
        const int st = kc % 3;
        CP_WAIT1();
        __syncthreads();
        if (kc + 2 < NKC) load_chunk((kc + 2) % 3, (kc + 2) * 32);
        CP_COMMIT();

        #pragma unroll
        for (int ks = 0; ks < 2; ks++) {
            uint32_t a[4];
            ldmx4(a, su(&Ws_s[st][(warp_m * 16 + l8 * 8 + l7) * WS
                                  + ks * 16 + l16 * 8]));
            #pragma unroll
            for (int nt = 0; nt < 4; nt++) {
                uint32_t bfr[2];
                ldmx2(bfr, su(&As_s[st][(warp_n * 32 + nt * 8 + l7) * WS
                                        + ks * 16 + l8 * 8]));
                mma16(acc[nt], a, bfr);
            }
        }
    }

    const int crow = c0 + warp_m * 16 + lg;
    const float bias0 = bo[crow];
    const float bias8 = bo[crow + 8];
    #pragma unroll
    for (int nt = 0; nt < 4; nt++) {
        int s = s0 + warp_n * 32 + nt * 8 + 2 * lt;
        *(float2*)&out[((size_t)b * C_DIM + crow) * HW + s] =
            make_float2(acc[nt][0] + bias0, acc[nt][1] + bias0);
        *(float2*)&out[((size_t)b * C_DIM + crow + 8) * HW + s] =
            make_float2(acc[nt][2] + bias8, acc[nt][3] + bias8);
    }
}

// ---------------------------------------------------------------------------
extern "C" void kernel_launch(void* const* d_in, const int* in_sizes, int n_in,
                              void* d_out, int out_size)
{
    const float* X  = (const float*)d_in[0];
    const float* Wq = (const float*)d_in[1];
    const float* bq = (const float*)d_in[2];
    const float* Wk = (const float*)d_in[3];
    const float* bk = (const float*)d_in[4];
    const float* Wv = (const float*)d_in[5];
    const float* bv = (const float*)d_in[6];
    const float* Wo = (const float*)d_in[7];
    const float* bo = (const float*)d_in[8];
    float* out = (float*)d_out;

    cvt_kernel<<<(NCVT / 8 + 255) / 256, 256>>>(X, Wq, Wk, Wv, Wo);
    qkv_kernel<<<dim3(HW / 64, BN), 256>>>(bq, bk, bv);
    attn_kernel<<<dim3(HW / QT, BN), 256>>>();
    proj_kernel<<<dim3(HW / 64, C_DIM / 64, BATCH), 256>>>(bo, out);
}